// round 1
// baseline (speedup 1.0000x reference)
#include <cuda_runtime.h>
#include <cuda_bf16.h>
#include <math.h>

// Problem dims (fixed by reference)
#define BB 2
#define NN 2048
#define DD 1024
#define HH 16
#define DHH 64
#define HID 4096
#define D3 3072
#define ROWS (BB*NN)          // 4096

// ---------------- scratch (static device arrays; no allocation) -------------
__device__ float g_xn[ROWS * DD];     // 16 MB  LN output (reused twice)
__device__ float g_qkv[ROWS * D3];    // 48 MB
__device__ float g_obuf[ROWS * DD];   // 16 MB  attention out in [B,H,N,Dh]
__device__ float g_x1[ROWS * DD];     // 16 MB  x + attn
__device__ float g_h[ROWS * HID];     // 64 MB  MLP hidden

// ---------------- block reduce helper ---------------------------------------
__device__ __forceinline__ float block_sum_256(float v) {
    __shared__ float red[8];
    #pragma unroll
    for (int o = 16; o; o >>= 1) v += __shfl_xor_sync(0xffffffffu, v, o);
    int w = threadIdx.x >> 5;
    if ((threadIdx.x & 31) == 0) red[w] = v;
    __syncthreads();
    v = red[threadIdx.x & 7];
    #pragma unroll
    for (int o = 4; o; o >>= 1) v += __shfl_xor_sync(0xffffffffu, v, o);
    __syncthreads();   // allow reuse of red[] by a subsequent call
    return v;
}

// ---------------- LayerNorm: one block (256 thr) per row of 1024 -------------
__global__ __launch_bounds__(256) void ln_kernel(const float* __restrict__ x,
                                                 const float* __restrict__ g,
                                                 const float* __restrict__ b,
                                                 float* __restrict__ out) {
    int row = blockIdx.x;
    const float4* xr = (const float4*)(x + (size_t)row * DD);
    float4 v = xr[threadIdx.x];
    float s = v.x + v.y + v.z + v.w;
    s = block_sum_256(s);
    float mu = s * (1.0f / DD);
    float dx = v.x - mu, dy = v.y - mu, dz = v.z - mu, dw = v.w - mu;
    float vs = dx*dx + dy*dy + dz*dz + dw*dw;
    vs = block_sum_256(vs);
    float rstd = rsqrtf(vs * (1.0f / DD) + 1e-5f);
    float4 gg = ((const float4*)g)[threadIdx.x];
    float4 bb = ((const float4*)b)[threadIdx.x];
    float4 o;
    o.x = dx * rstd * gg.x + bb.x;
    o.y = dy * rstd * gg.y + bb.y;
    o.z = dz * rstd * gg.z + bb.z;
    o.w = dw * rstd * gg.w + bb.w;
    ((float4*)(out + (size_t)row * DD))[threadIdx.x] = o;
}

// ---------------- elementwise residual add ----------------------------------
__global__ __launch_bounds__(256) void add_kernel(const float* __restrict__ a,
                                                  const float* __restrict__ b,
                                                  float* __restrict__ o) {
    int i = blockIdx.x * 256 + threadIdx.x;
    float4 va = ((const float4*)a)[i];
    float4 vb = ((const float4*)b)[i];
    va.x += vb.x; va.y += vb.y; va.z += vb.z; va.w += vb.w;
    ((float4*)o)[i] = va;
}

// ---------------- SGEMM: C = A(MxK) @ B(KxN) + bias, optional epilogue -------
// EPI: 0 = bias, 1 = bias + exact GELU, 2 = bias + residual add
#define BM 128
#define BN 128
#define BK 16

template<int EPI>
__global__ __launch_bounds__(256) void sgemm_kernel(const float* __restrict__ A,
                                                    const float* __restrict__ B,
                                                    const float* __restrict__ bias,
                                                    const float* __restrict__ res,
                                                    float* __restrict__ C,
                                                    int M, int N, int K) {
    __shared__ float As[BK][BM];
    __shared__ float Bs[BK][BN];
    int tid = threadIdx.x;
    int tx = tid & 15;
    int ty = tid >> 4;
    int row0 = blockIdx.y * BM;
    int col0 = blockIdx.x * BN;

    float c[8][8];
    #pragma unroll
    for (int i = 0; i < 8; i++)
        #pragma unroll
        for (int j = 0; j < 8; j++) c[i][j] = 0.0f;

    for (int k0 = 0; k0 < K; k0 += BK) {
        // load A tile (128x16) transposed, B tile (16x128) straight
        #pragma unroll
        for (int l = 0; l < 2; l++) {
            int f = tid + l * 256;            // float4 index 0..511
            int ar = f >> 2;                  // 0..127
            int ac = (f & 3) * 4;             // 0,4,8,12
            float4 va = *(const float4*)&A[(size_t)(row0 + ar) * K + k0 + ac];
            As[ac + 0][ar] = va.x;
            As[ac + 1][ar] = va.y;
            As[ac + 2][ar] = va.z;
            As[ac + 3][ar] = va.w;
            int br = f >> 5;                  // 0..15
            int bc = (f & 31) * 4;            // 0..124
            *(float4*)&Bs[br][bc] = *(const float4*)&B[(size_t)(k0 + br) * N + col0 + bc];
        }
        __syncthreads();
        #pragma unroll
        for (int kk = 0; kk < BK; kk++) {
            float a[8], b[8];
            *(float4*)&a[0] = *(float4*)&As[kk][ty * 4];
            *(float4*)&a[4] = *(float4*)&As[kk][ty * 4 + 64];
            *(float4*)&b[0] = *(float4*)&Bs[kk][tx * 4];
            *(float4*)&b[4] = *(float4*)&Bs[kk][tx * 4 + 64];
            #pragma unroll
            for (int i = 0; i < 8; i++)
                #pragma unroll
                for (int j = 0; j < 8; j++)
                    c[i][j] = fmaf(a[i], b[j], c[i][j]);
        }
        __syncthreads();
    }

    // epilogue: rows at ty*4 + {0..3} and +64; cols at tx*4 + {0..3} and +64
    #pragma unroll
    for (int i = 0; i < 8; i++) {
        int row = row0 + ty * 4 + (i & 3) + ((i >> 2) * 64);
        #pragma unroll
        for (int jg = 0; jg < 2; jg++) {
            int col = col0 + tx * 4 + jg * 64;
            float4 o;
            float vv[4];
            #pragma unroll
            for (int j = 0; j < 4; j++) {
                float v = c[i][jg * 4 + j] + bias[col + j];
                if (EPI == 1) {
                    v = 0.5f * v * (1.0f + erff(v * 0.70710678118654752f));
                } else if (EPI == 2) {
                    v += res[(size_t)row * N + col + j];
                }
                vv[j] = v;
            }
            o.x = vv[0]; o.y = vv[1]; o.z = vv[2]; o.w = vv[3];
            *(float4*)&C[(size_t)row * N + col] = o;
        }
    }
}

// ---------------- flash attention (fp32, no 1/sqrt(Dh) scaling) --------------
// grid: (N/64, B*H); block 256 threads. S tile 64x64, thread tile 4x4.
// Output written in [B, H, N, Dh] contiguous layout (matches raw reshape).
__global__ __launch_bounds__(256) void attn_kernel(const float* __restrict__ qkv,
                                                   float* __restrict__ obuf) {
    __shared__ float Qs[64 * 64];
    __shared__ float KPs[64 * 64];   // K (transposed+swizzled), then P
    __shared__ float Vs[64 * 64];

    int bh = blockIdx.y;
    int b = bh >> 4;
    int h = bh & 15;
    int q0 = blockIdx.x * 64;
    int tid = threadIdx.x;
    int tx = tid & 15;
    int ty = tid >> 4;

    const float* qbase = qkv + (size_t)b * NN * D3 + h * DHH;
    const float* kbase = qbase + DD;
    const float* vbase = qbase + 2 * DD;

    // load Q tile [64 x 64]
    #pragma unroll
    for (int l = 0; l < 4; l++) {
        int f = tid + l * 256;
        int r = f >> 4;
        int cc = (f & 15) * 4;
        *(float4*)&Qs[r * 64 + cc] =
            *(const float4*)&qbase[(size_t)(q0 + r) * D3 + cc];
    }

    float m[4], lsum[4], acc[4][4];
    #pragma unroll
    for (int i = 0; i < 4; i++) {
        m[i] = -1e30f;
        lsum[i] = 0.0f;
        #pragma unroll
        for (int j = 0; j < 4; j++) acc[i][j] = 0.0f;
    }

    for (int kt = 0; kt < NN; kt += 64) {
        __syncthreads();
        // load K (transposed w/ XOR swizzle: element (dh, key) at [dh*64 + (key^dh&31)])
        // and V straight [key][dh]
        #pragma unroll
        for (int l = 0; l < 4; l++) {
            int f = tid + l * 256;
            int r = f >> 4;             // key index within tile
            int cc = (f & 15) * 4;      // dh
            float4 kv = *(const float4*)&kbase[(size_t)(kt + r) * D3 + cc];
            KPs[(cc + 0) * 64 + (r ^ ((cc + 0) & 31))] = kv.x;
            KPs[(cc + 1) * 64 + (r ^ ((cc + 1) & 31))] = kv.y;
            KPs[(cc + 2) * 64 + (r ^ ((cc + 2) & 31))] = kv.z;
            KPs[(cc + 3) * 64 + (r ^ ((cc + 3) & 31))] = kv.w;
            *(float4*)&Vs[r * 64 + cc] =
                *(const float4*)&vbase[(size_t)(kt + r) * D3 + cc];
        }
        __syncthreads();

        // S = Q @ K^T for this thread's 4x4 tile
        float s[4][4];
        #pragma unroll
        for (int i = 0; i < 4; i++)
            #pragma unroll
            for (int j = 0; j < 4; j++) s[i][j] = 0.0f;
        #pragma unroll
        for (int kk = 0; kk < 64; kk++) {
            float kf[4];
            int sw = kk & 31;
            #pragma unroll
            for (int j = 0; j < 4; j++)
                kf[j] = KPs[kk * 64 + ((tx * 4 + j) ^ sw)];
            #pragma unroll
            for (int i = 0; i < 4; i++) {
                float qv = Qs[(ty * 4 + i) * 64 + kk];
                #pragma unroll
                for (int j = 0; j < 4; j++)
                    s[i][j] = fmaf(qv, kf[j], s[i][j]);
            }
        }

        // online softmax (rows owned by the 16 tx-threads of each half-warp)
        #pragma unroll
        for (int i = 0; i < 4; i++) {
            float mt = fmaxf(fmaxf(s[i][0], s[i][1]), fmaxf(s[i][2], s[i][3]));
            #pragma unroll
            for (int o = 8; o; o >>= 1)
                mt = fmaxf(mt, __shfl_xor_sync(0xffffffffu, mt, o, 16));
            float mn = fmaxf(m[i], mt);
            float scale = __expf(m[i] - mn);
            m[i] = mn;
            float rs = 0.0f;
            #pragma unroll
            for (int j = 0; j < 4; j++) {
                s[i][j] = __expf(s[i][j] - mn);
                rs += s[i][j];
            }
            #pragma unroll
            for (int o = 8; o; o >>= 1)
                rs += __shfl_xor_sync(0xffffffffu, rs, o, 16);
            lsum[i] = lsum[i] * scale + rs;
            #pragma unroll
            for (int j = 0; j < 4; j++) acc[i][j] *= scale;
        }

        __syncthreads();
        // write P into KPs (plain row-major)
        #pragma unroll
        for (int i = 0; i < 4; i++) {
            float4 p4;
            p4.x = s[i][0]; p4.y = s[i][1]; p4.z = s[i][2]; p4.w = s[i][3];
            *(float4*)&KPs[(ty * 4 + i) * 64 + tx * 4] = p4;
        }
        __syncthreads();

        // acc += P @ V
        #pragma unroll
        for (int cc = 0; cc < 64; cc++) {
            float4 vf = *(float4*)&Vs[cc * 64 + tx * 4];
            #pragma unroll
            for (int i = 0; i < 4; i++) {
                float pv = KPs[(ty * 4 + i) * 64 + cc];
                acc[i][0] = fmaf(pv, vf.x, acc[i][0]);
                acc[i][1] = fmaf(pv, vf.y, acc[i][1]);
                acc[i][2] = fmaf(pv, vf.z, acc[i][2]);
                acc[i][3] = fmaf(pv, vf.w, acc[i][3]);
            }
        }
    }

    // normalize and store to [B, H, N, Dh] contiguous
    float* ob = obuf + ((size_t)bh * NN + q0) * DHH;
    #pragma unroll
    for (int i = 0; i < 4; i++) {
        float inv = 1.0f / lsum[i];
        int r = ty * 4 + i;
        float4 o4;
        o4.x = acc[i][0] * inv;
        o4.y = acc[i][1] * inv;
        o4.z = acc[i][2] * inv;
        o4.w = acc[i][3] * inv;
        *(float4*)&ob[r * DHH + tx * 4] = o4;
    }
}

// ---------------- launch ------------------------------------------------------
extern "C" void kernel_launch(void* const* d_in, const int* in_sizes, int n_in,
                              void* d_out, int out_size) {
    const float* x     = (const float*)d_in[0];
    const float* w_qkv = (const float*)d_in[1];
    const float* b_qkv = (const float*)d_in[2];
    const float* ln_g  = (const float*)d_in[3];
    const float* ln_b  = (const float*)d_in[4];
    const float* w1    = (const float*)d_in[5];
    const float* b1    = (const float*)d_in[6];
    const float* w2    = (const float*)d_in[7];
    const float* b2    = (const float*)d_in[8];
    float* out = (float*)d_out;

    float *xn, *qkv, *obuf, *x1, *hbuf;
    cudaGetSymbolAddress((void**)&xn,   g_xn);
    cudaGetSymbolAddress((void**)&qkv,  g_qkv);
    cudaGetSymbolAddress((void**)&obuf, g_obuf);
    cudaGetSymbolAddress((void**)&x1,   g_x1);
    cudaGetSymbolAddress((void**)&hbuf, g_h);

    // 1. xn = LN(x)
    ln_kernel<<<ROWS, 256>>>(x, ln_g, ln_b, xn);
    // 2. qkv = xn @ w_qkv + b_qkv
    sgemm_kernel<0><<<dim3(D3 / BN, ROWS / BM), 256>>>(xn, w_qkv, b_qkv, nullptr,
                                                       qkv, ROWS, D3, DD);
    // 3. attention -> obuf [B,H,N,Dh]
    attn_kernel<<<dim3(NN / 64, BB * HH), 256>>>(qkv, obuf);
    // 4. x1 = x + obuf (raw reshape == flat add)
    add_kernel<<<(ROWS * DD) / (256 * 4), 256>>>(x, obuf, x1);
    // 5. xn = LN(x1)
    ln_kernel<<<ROWS, 256>>>(x1, ln_g, ln_b, xn);
    // 6. h = gelu(xn @ w1 + b1)
    sgemm_kernel<1><<<dim3(HID / BN, ROWS / BM), 256>>>(xn, w1, b1, nullptr,
                                                        hbuf, ROWS, HID, DD);
    // 7. out = x1 + h @ w2 + b2
    sgemm_kernel<2><<<dim3(DD / BN, ROWS / BM), 256>>>(hbuf, w2, b2, x1,
                                                       out, ROWS, DD, HID);
}

// round 3
// speedup vs baseline: 1.5105x; 1.5105x over previous
#include <cuda_runtime.h>
#include <cuda_bf16.h>
#include <math.h>
#include <stdint.h>

// Problem dims (fixed by reference)
#define BB 2
#define NN 2048
#define DD 1024
#define HH 16
#define DHH 64
#define HID 4096
#define D3 3072
#define ROWS (BB*NN)          // 4096

// ---------------- scratch (static device arrays; no allocation) -------------
__device__ float g_xn[ROWS * DD];      // LN output (reused twice)
__device__ float g_qkv[ROWS * D3];
__device__ float g_obuf[ROWS * DD];    // attention out in [B,H,N,Dh]
__device__ float g_x1[ROWS * DD];      // x + attn
__device__ float g_h[ROWS * HID];      // MLP hidden
__device__ float g_wqkvT[D3 * DD];     // transposed weights (K-major B operand)
__device__ float g_w1T[HID * DD];
__device__ float g_w2T[DD * HID];

// ======================= mma.sync tf32 GEMM ==================================
// C[M,N] = A[M,K] @ BT[N,K]^T + bias; EPI: 0 bias, 1 gelu, 2 +res
// CTA tile 128x128x32, 256 threads (8 warps, 2x4), warp tile 64x32.
// SMEM holds tiles in *fragment order* so frag loads are 1 vector LDS each.

#define AST 132                         // A frag-block stride in floats (528B, 16B-aligned)
#define BST 66                          // B frag-block stride in floats (264B, 8B-aligned)
#define A_STAGE_F (32 * AST)            // 32 A-frag blocks / stage
#define B_STAGE_F (64 * BST)            // 64 B-frag blocks / stage
#define STAGE_F (A_STAGE_F + B_STAGE_F)
#define GEMM_SMEM_BYTES (2 * STAGE_F * 4)   // 67584 B

__device__ __forceinline__ uint32_t f2tf32(float x) {
    uint32_t u;
    asm("cvt.rna.tf32.f32 %0, %1;" : "=r"(u) : "f"(x));
    return u;
}

__device__ __forceinline__ void mma_tf32(float* c, const uint32_t* a, const uint32_t* b) {
    asm volatile(
        "mma.sync.aligned.m16n8k8.row.col.f32.tf32.tf32.f32 "
        "{%0,%1,%2,%3}, {%4,%5,%6,%7}, {%8,%9}, {%0,%1,%2,%3};"
        : "+f"(c[0]), "+f"(c[1]), "+f"(c[2]), "+f"(c[3])
        : "r"(a[0]), "r"(a[1]), "r"(a[2]), "r"(a[3]), "r"(b[0]), "r"(b[1]));
}

// global -> regs (8 float4 per thread: 4 A rows-chunks, 4 B rows-chunks)
__device__ __forceinline__ void gload(const float* __restrict__ A,
                                      const float* __restrict__ BT,
                                      int K, int row0, int col0, int k0,
                                      int tid, float4* av, float4* bv) {
    #pragma unroll
    for (int l = 0; l < 4; l++) {
        int f = tid + l * 256;          // 0..1023
        int r = f >> 3;                 // 0..127
        int i = f & 7;                  // float4 index in 32-wide k chunk
        av[l] = *(const float4*)&A [(size_t)(row0 + r) * K + k0 + i * 4];
        bv[l] = *(const float4*)&BT[(size_t)(col0 + r) * K + k0 + i * 4];
    }
}

// regs -> smem stage, converting to tf32, scattering to fragment order
__device__ __forceinline__ void stage_store(uint32_t* sA, uint32_t* sB,
                                            const float4* av, const float4* bv,
                                            int tid) {
    #pragma unroll
    for (int l = 0; l < 4; l++) {
        int f = tid + l * 256;
        int r = f >> 3;                 // A row / B row(n)
        int i = f & 7;
        int ks = i >> 1;                // k-step 0..3
        // --- A element (r, i*4+q): block fa=(r>>4)*4+ks, lane=(r&7)*4+q,
        //     reg = (i&1)*2 + ((r&15)>=8)
        {
            int fa = (r >> 4) * 4 + ks;
            int regid = (i & 1) * 2 + ((r & 15) >= 8 ? 1 : 0);
            uint32_t* base = sA + fa * AST + regid;
            int ln0 = (r & 7) * 4;
            base[(ln0 + 0) * 4] = f2tf32(av[l].x);
            base[(ln0 + 1) * 4] = f2tf32(av[l].y);
            base[(ln0 + 2) * 4] = f2tf32(av[l].z);
            base[(ln0 + 3) * 4] = f2tf32(av[l].w);
        }
        // --- B element (n=r, k=i*4+q): block fb=(n>>3)*4+ks, lane=(n&7)*4+q,
        //     reg = i&1
        {
            int fb = (r >> 3) * 4 + ks;
            int regid = i & 1;
            uint32_t* base = sB + fb * BST + regid;
            int ln0 = (r & 7) * 4;
            base[(ln0 + 0) * 2] = f2tf32(bv[l].x);
            base[(ln0 + 1) * 2] = f2tf32(bv[l].y);
            base[(ln0 + 2) * 2] = f2tf32(bv[l].z);
            base[(ln0 + 3) * 2] = f2tf32(bv[l].w);
        }
    }
}

template<int EPI>
__global__ __launch_bounds__(256) void gemm_mma(const float* __restrict__ A,
                                                const float* __restrict__ BT,
                                                const float* __restrict__ bias,
                                                const float* __restrict__ res,
                                                float* __restrict__ C,
                                                int M, int N, int K) {
    extern __shared__ uint32_t sm[];
    uint32_t* stA[2] = { sm,              sm + STAGE_F };
    uint32_t* stB[2] = { sm + A_STAGE_F,  sm + STAGE_F + A_STAGE_F };

    int tid = threadIdx.x;
    int lane = tid & 31, wid = tid >> 5;
    int warpM = wid & 1, warpN = wid >> 1;     // 2 x 4
    int row0 = blockIdx.y * 128, col0 = blockIdx.x * 128;

    float c[4][4][4];
    #pragma unroll
    for (int mf = 0; mf < 4; mf++)
        #pragma unroll
        for (int nf = 0; nf < 4; nf++)
            #pragma unroll
            for (int q = 0; q < 4; q++) c[mf][nf][q] = 0.0f;

    int nk = K / 32;
    {
        float4 av[4], bv[4];
        gload(A, BT, K, row0, col0, 0, tid, av, bv);
        stage_store(stA[0], stB[0], av, bv, tid);
    }
    __syncthreads();

    for (int kt = 0; kt < nk; kt++) {
        int s = kt & 1;
        float4 av[4], bv[4];
        if (kt + 1 < nk)
            gload(A, BT, K, row0, col0, (kt + 1) * 32, tid, av, bv);

        uint32_t* sA = stA[s];
        uint32_t* sB = stB[s];
        #pragma unroll
        for (int ss = 0; ss < 4; ss++) {
            uint32_t a[4][4], b[4][2];
            #pragma unroll
            for (int mf = 0; mf < 4; mf++) {
                int fa = (warpM * 4 + mf) * 4 + ss;
                uint4 v = *(uint4*)&sA[fa * AST + lane * 4];
                a[mf][0] = v.x; a[mf][1] = v.y; a[mf][2] = v.z; a[mf][3] = v.w;
            }
            #pragma unroll
            for (int nf = 0; nf < 4; nf++) {
                int fb = (warpN * 4 + nf) * 4 + ss;
                uint2 v = *(uint2*)&sB[fb * BST + lane * 2];
                b[nf][0] = v.x; b[nf][1] = v.y;
            }
            #pragma unroll
            for (int mf = 0; mf < 4; mf++)
                #pragma unroll
                for (int nf = 0; nf < 4; nf++)
                    mma_tf32(c[mf][nf], a[mf], b[nf]);
        }

        if (kt + 1 < nk) {
            stage_store(stA[s ^ 1], stB[s ^ 1], av, bv, tid);
            __syncthreads();
        }
    }

    // ---------------- epilogue ----------------
    int gid = lane >> 2, tig = lane & 3;
    #pragma unroll
    for (int mf = 0; mf < 4; mf++) {
        #pragma unroll
        for (int nf = 0; nf < 4; nf++) {
            int col = col0 + warpN * 32 + nf * 8 + tig * 2;
            float b0 = bias[col], b1 = bias[col + 1];
            #pragma unroll
            for (int h = 0; h < 2; h++) {
                int row = row0 + warpM * 64 + mf * 16 + gid + h * 8;
                float v0 = c[mf][nf][h * 2 + 0] + b0;
                float v1 = c[mf][nf][h * 2 + 1] + b1;
                if (EPI == 1) {
                    v0 = 0.5f * v0 * (1.0f + erff(v0 * 0.70710678118654752f));
                    v1 = 0.5f * v1 * (1.0f + erff(v1 * 0.70710678118654752f));
                } else if (EPI == 2) {
                    float2 rr = *(const float2*)&res[(size_t)row * N + col];
                    v0 += rr.x; v1 += rr.y;
                }
                float2 o; o.x = v0; o.y = v1;
                *(float2*)&C[(size_t)row * N + col] = o;
            }
        }
    }
}

// ---------------- weight transpose: out[C][R] = in[R][C] ---------------------
__global__ __launch_bounds__(256) void transpose_kernel(const float* __restrict__ in,
                                                        float* __restrict__ out,
                                                        int R, int C) {
    __shared__ float t[32][33];
    int c0 = blockIdx.x * 32, r0 = blockIdx.y * 32;
    int tx = threadIdx.x & 31, ty8 = threadIdx.x >> 5;   // 32 x 8
    #pragma unroll
    for (int l = 0; l < 4; l++) {
        int r = ty8 + l * 8;
        t[r][tx] = in[(size_t)(r0 + r) * C + c0 + tx];
    }
    __syncthreads();
    #pragma unroll
    for (int l = 0; l < 4; l++) {
        int r = ty8 + l * 8;
        out[(size_t)(c0 + r) * R + r0 + tx] = t[tx][r];
    }
}

// ---------------- block reduce helper ---------------------------------------
__device__ __forceinline__ float block_sum_256(float v) {
    __shared__ float red[8];
    #pragma unroll
    for (int o = 16; o; o >>= 1) v += __shfl_xor_sync(0xffffffffu, v, o);
    int w = threadIdx.x >> 5;
    if ((threadIdx.x & 31) == 0) red[w] = v;
    __syncthreads();
    v = red[threadIdx.x & 7];
    #pragma unroll
    for (int o = 4; o; o >>= 1) v += __shfl_xor_sync(0xffffffffu, v, o);
    __syncthreads();
    return v;
}

// ---------------- LayerNorm ---------------------------------------------------
__global__ __launch_bounds__(256) void ln_kernel(const float* __restrict__ x,
                                                 const float* __restrict__ g,
                                                 const float* __restrict__ b,
                                                 float* __restrict__ out) {
    int row = blockIdx.x;
    const float4* xr = (const float4*)(x + (size_t)row * DD);
    float4 v = xr[threadIdx.x];
    float s = v.x + v.y + v.z + v.w;
    s = block_sum_256(s);
    float mu = s * (1.0f / DD);
    float dx = v.x - mu, dy = v.y - mu, dz = v.z - mu, dw = v.w - mu;
    float vs = dx*dx + dy*dy + dz*dz + dw*dw;
    vs = block_sum_256(vs);
    float rstd = rsqrtf(vs * (1.0f / DD) + 1e-5f);
    float4 gg = ((const float4*)g)[threadIdx.x];
    float4 bb = ((const float4*)b)[threadIdx.x];
    float4 o;
    o.x = dx * rstd * gg.x + bb.x;
    o.y = dy * rstd * gg.y + bb.y;
    o.z = dz * rstd * gg.z + bb.z;
    o.w = dw * rstd * gg.w + bb.w;
    ((float4*)(out + (size_t)row * DD))[threadIdx.x] = o;
}

// ---------------- elementwise residual add ----------------------------------
__global__ __launch_bounds__(256) void add_kernel(const float* __restrict__ a,
                                                  const float* __restrict__ b,
                                                  float* __restrict__ o) {
    int i = blockIdx.x * 256 + threadIdx.x;
    float4 va = ((const float4*)a)[i];
    float4 vb = ((const float4*)b)[i];
    va.x += vb.x; va.y += vb.y; va.z += vb.z; va.w += vb.w;
    ((float4*)o)[i] = va;
}

// ---------------- flash attention (fp32 SIMT) --------------------------------
__global__ __launch_bounds__(256) void attn_kernel(const float* __restrict__ qkv,
                                                   float* __restrict__ obuf) {
    __shared__ float Qs[64 * 64];
    __shared__ float KPs[64 * 64];
    __shared__ float Vs[64 * 64];

    int bh = blockIdx.y;
    int b = bh >> 4;
    int h = bh & 15;
    int q0 = blockIdx.x * 64;
    int tid = threadIdx.x;
    int tx = tid & 15;
    int ty = tid >> 4;

    const float* qbase = qkv + (size_t)b * NN * D3 + h * DHH;
    const float* kbase = qbase + DD;
    const float* vbase = qbase + 2 * DD;

    #pragma unroll
    for (int l = 0; l < 4; l++) {
        int f = tid + l * 256;
        int r = f >> 4;
        int cc = (f & 15) * 4;
        *(float4*)&Qs[r * 64 + cc] =
            *(const float4*)&qbase[(size_t)(q0 + r) * D3 + cc];
    }

    float m[4], lsum[4], acc[4][4];
    #pragma unroll
    for (int i = 0; i < 4; i++) {
        m[i] = -1e30f;
        lsum[i] = 0.0f;
        #pragma unroll
        for (int j = 0; j < 4; j++) acc[i][j] = 0.0f;
    }

    for (int kt = 0; kt < NN; kt += 64) {
        __syncthreads();
        #pragma unroll
        for (int l = 0; l < 4; l++) {
            int f = tid + l * 256;
            int r = f >> 4;
            int cc = (f & 15) * 4;
            float4 kv = *(const float4*)&kbase[(size_t)(kt + r) * D3 + cc];
            KPs[(cc + 0) * 64 + (r ^ ((cc + 0) & 31))] = kv.x;
            KPs[(cc + 1) * 64 + (r ^ ((cc + 1) & 31))] = kv.y;
            KPs[(cc + 2) * 64 + (r ^ ((cc + 2) & 31))] = kv.z;
            KPs[(cc + 3) * 64 + (r ^ ((cc + 3) & 31))] = kv.w;
            *(float4*)&Vs[r * 64 + cc] =
                *(const float4*)&vbase[(size_t)(kt + r) * D3 + cc];
        }
        __syncthreads();

        float s[4][4];
        #pragma unroll
        for (int i = 0; i < 4; i++)
            #pragma unroll
            for (int j = 0; j < 4; j++) s[i][j] = 0.0f;
        #pragma unroll
        for (int kk = 0; kk < 64; kk++) {
            float kf[4];
            int sw = kk & 31;
            #pragma unroll
            for (int j = 0; j < 4; j++)
                kf[j] = KPs[kk * 64 + ((tx * 4 + j) ^ sw)];
            #pragma unroll
            for (int i = 0; i < 4; i++) {
                float qv = Qs[(ty * 4 + i) * 64 + kk];
                #pragma unroll
                for (int j = 0; j < 4; j++)
                    s[i][j] = fmaf(qv, kf[j], s[i][j]);
            }
        }

        #pragma unroll
        for (int i = 0; i < 4; i++) {
            float mt = fmaxf(fmaxf(s[i][0], s[i][1]), fmaxf(s[i][2], s[i][3]));
            #pragma unroll
            for (int o = 8; o; o >>= 1)
                mt = fmaxf(mt, __shfl_xor_sync(0xffffffffu, mt, o, 16));
            float mn = fmaxf(m[i], mt);
            float scale = __expf(m[i] - mn);
            m[i] = mn;
            float rs = 0.0f;
            #pragma unroll
            for (int j = 0; j < 4; j++) {
                s[i][j] = __expf(s[i][j] - mn);
                rs += s[i][j];
            }
            #pragma unroll
            for (int o = 8; o; o >>= 1)
                rs += __shfl_xor_sync(0xffffffffu, rs, o, 16);
            lsum[i] = lsum[i] * scale + rs;
            #pragma unroll
            for (int j = 0; j < 4; j++) acc[i][j] *= scale;
        }

        __syncthreads();
        #pragma unroll
        for (int i = 0; i < 4; i++) {
            float4 p4;
            p4.x = s[i][0]; p4.y = s[i][1]; p4.z = s[i][2]; p4.w = s[i][3];
            *(float4*)&KPs[(ty * 4 + i) * 64 + tx * 4] = p4;
        }
        __syncthreads();

        #pragma unroll
        for (int cc = 0; cc < 64; cc++) {
            float4 vf = *(float4*)&Vs[cc * 64 + tx * 4];
            #pragma unroll
            for (int i = 0; i < 4; i++) {
                float pv = KPs[(ty * 4 + i) * 64 + cc];
                acc[i][0] = fmaf(pv, vf.x, acc[i][0]);
                acc[i][1] = fmaf(pv, vf.y, acc[i][1]);
                acc[i][2] = fmaf(pv, vf.z, acc[i][2]);
                acc[i][3] = fmaf(pv, vf.w, acc[i][3]);
            }
        }
    }

    float* ob = obuf + ((size_t)bh * NN + q0) * DHH;
    #pragma unroll
    for (int i = 0; i < 4; i++) {
        float inv = 1.0f / lsum[i];
        int r = ty * 4 + i;
        float4 o4;
        o4.x = acc[i][0] * inv;
        o4.y = acc[i][1] * inv;
        o4.z = acc[i][2] * inv;
        o4.w = acc[i][3] * inv;
        *(float4*)&ob[r * DHH + tx * 4] = o4;
    }
}

// ---------------- launch ------------------------------------------------------
extern "C" void kernel_launch(void* const* d_in, const int* in_sizes, int n_in,
                              void* d_out, int out_size) {
    const float* x     = (const float*)d_in[0];
    const float* w_qkv = (const float*)d_in[1];
    const float* b_qkv = (const float*)d_in[2];
    const float* ln_g  = (const float*)d_in[3];
    const float* ln_b  = (const float*)d_in[4];
    const float* w1    = (const float*)d_in[5];
    const float* b1    = (const float*)d_in[6];
    const float* w2    = (const float*)d_in[7];
    const float* b2    = (const float*)d_in[8];
    float* out = (float*)d_out;

    float *xn, *qkv, *obuf, *x1, *hbuf, *wqkvT, *w1T, *w2T;
    cudaGetSymbolAddress((void**)&xn,    g_xn);
    cudaGetSymbolAddress((void**)&qkv,   g_qkv);
    cudaGetSymbolAddress((void**)&obuf,  g_obuf);
    cudaGetSymbolAddress((void**)&x1,    g_x1);
    cudaGetSymbolAddress((void**)&hbuf,  g_h);
    cudaGetSymbolAddress((void**)&wqkvT, g_wqkvT);
    cudaGetSymbolAddress((void**)&w1T,   g_w1T);
    cudaGetSymbolAddress((void**)&w2T,   g_w2T);

    cudaFuncSetAttribute(gemm_mma<0>, cudaFuncAttributeMaxDynamicSharedMemorySize, GEMM_SMEM_BYTES);
    cudaFuncSetAttribute(gemm_mma<1>, cudaFuncAttributeMaxDynamicSharedMemorySize, GEMM_SMEM_BYTES);
    cudaFuncSetAttribute(gemm_mma<2>, cudaFuncAttributeMaxDynamicSharedMemorySize, GEMM_SMEM_BYTES);

    // 0. transpose weights (K-major B operands)
    transpose_kernel<<<dim3(D3 / 32, DD / 32), 256>>>(w_qkv, wqkvT, DD, D3);
    transpose_kernel<<<dim3(HID / 32, DD / 32), 256>>>(w1, w1T, DD, HID);
    transpose_kernel<<<dim3(DD / 32, HID / 32), 256>>>(w2, w2T, HID, DD);

    // 1. xn = LN(x)
    ln_kernel<<<ROWS, 256>>>(x, ln_g, ln_b, xn);
    // 2. qkv = xn @ w_qkv + b_qkv
    gemm_mma<0><<<dim3(D3 / 128, ROWS / 128), 256, GEMM_SMEM_BYTES>>>(
        xn, wqkvT, b_qkv, nullptr, qkv, ROWS, D3, DD);
    // 3. attention -> obuf [B,H,N,Dh]
    attn_kernel<<<dim3(NN / 64, BB * HH), 256>>>(qkv, obuf);
    // 4. x1 = x + obuf (raw reshape == flat add)
    add_kernel<<<(ROWS * DD) / (256 * 4), 256>>>(x, obuf, x1);
    // 5. xn = LN(x1)
    ln_kernel<<<ROWS, 256>>>(x1, ln_g, ln_b, xn);
    // 6. h = gelu(xn @ w1 + b1)
    gemm_mma<1><<<dim3(HID / 128, ROWS / 128), 256, GEMM_SMEM_BYTES>>>(
        xn, w1T, b1, nullptr, hbuf, ROWS, HID, DD);
    // 7. out = x1 + h @ w2 + b2
    gemm_mma<2><<<dim3(DD / 128, ROWS / 128), 256, GEMM_SMEM_BYTES>>>(
        hbuf, w2T, b2, x1, out, ROWS, DD, HID);
}

// round 4
// speedup vs baseline: 2.1743x; 1.4394x over previous
#include <cuda_runtime.h>
#include <cuda_bf16.h>
#include <math.h>
#include <stdint.h>

// Problem dims (fixed by reference)
#define BB 2
#define NN 2048
#define DD 1024
#define HH 16
#define DHH 64
#define HID 4096
#define D3 3072
#define ROWS (BB*NN)          // 4096

// ---------------- scratch (static device arrays; no allocation) -------------
__device__ float g_xn[ROWS * DD];      // LN output (reused twice)
__device__ float g_qkv[ROWS * D3];
__device__ float g_x1[ROWS * DD];      // x + attn
__device__ float g_h[ROWS * HID];      // MLP hidden
__device__ float g_wqkvT[D3 * DD];     // transposed weights (K-major B operand)
__device__ float g_w1T[HID * DD];
__device__ float g_w2T[DD * HID];

// ======================= common mma helpers ==================================
__device__ __forceinline__ uint32_t f2tf32(float x) {
    uint32_t u;
    asm("cvt.rna.tf32.f32 %0, %1;" : "=r"(u) : "f"(x));
    return u;
}

__device__ __forceinline__ void mma_tf32(float* c, const uint32_t* a, const uint32_t* b) {
    asm volatile(
        "mma.sync.aligned.m16n8k8.row.col.f32.tf32.tf32.f32 "
        "{%0,%1,%2,%3}, {%4,%5,%6,%7}, {%8,%9}, {%0,%1,%2,%3};"
        : "+f"(c[0]), "+f"(c[1]), "+f"(c[2]), "+f"(c[3])
        : "r"(a[0]), "r"(a[1]), "r"(a[2]), "r"(a[3]), "r"(b[0]), "r"(b[1]));
}

// ======================= mma.sync tf32 GEMM ==================================
// C[M,N] = A[M,K] @ BT[N,K]^T + bias; EPI: 0 bias, 1 gelu, 2 +res
// CTA tile 128x128x32, 256 threads (8 warps, 2x4), warp tile 64x32.

#define AST 132
#define BST 66
#define A_STAGE_F (32 * AST)
#define B_STAGE_F (64 * BST)
#define STAGE_F (A_STAGE_F + B_STAGE_F)
#define GEMM_SMEM_BYTES (2 * STAGE_F * 4)   // 67584 B

__device__ __forceinline__ void gload(const float* __restrict__ A,
                                      const float* __restrict__ BT,
                                      int K, int row0, int col0, int k0,
                                      int tid, float4* av, float4* bv) {
    #pragma unroll
    for (int l = 0; l < 4; l++) {
        int f = tid + l * 256;
        int r = f >> 3;
        int i = f & 7;
        av[l] = *(const float4*)&A [(size_t)(row0 + r) * K + k0 + i * 4];
        bv[l] = *(const float4*)&BT[(size_t)(col0 + r) * K + k0 + i * 4];
    }
}

__device__ __forceinline__ void stage_store(uint32_t* sA, uint32_t* sB,
                                            const float4* av, const float4* bv,
                                            int tid) {
    #pragma unroll
    for (int l = 0; l < 4; l++) {
        int f = tid + l * 256;
        int r = f >> 3;
        int i = f & 7;
        int ks = i >> 1;
        {
            int fa = (r >> 4) * 4 + ks;
            int regid = (i & 1) * 2 + ((r & 15) >= 8 ? 1 : 0);
            uint32_t* base = sA + fa * AST + regid;
            int ln0 = (r & 7) * 4;
            base[(ln0 + 0) * 4] = f2tf32(av[l].x);
            base[(ln0 + 1) * 4] = f2tf32(av[l].y);
            base[(ln0 + 2) * 4] = f2tf32(av[l].z);
            base[(ln0 + 3) * 4] = f2tf32(av[l].w);
        }
        {
            int fb = (r >> 3) * 4 + ks;
            int regid = i & 1;
            uint32_t* base = sB + fb * BST + regid;
            int ln0 = (r & 7) * 4;
            base[(ln0 + 0) * 2] = f2tf32(bv[l].x);
            base[(ln0 + 1) * 2] = f2tf32(bv[l].y);
            base[(ln0 + 2) * 2] = f2tf32(bv[l].z);
            base[(ln0 + 3) * 2] = f2tf32(bv[l].w);
        }
    }
}

template<int EPI>
__global__ __launch_bounds__(256) void gemm_mma(const float* __restrict__ A,
                                                const float* __restrict__ BT,
                                                const float* __restrict__ bias,
                                                const float* __restrict__ res,
                                                float* __restrict__ C,
                                                int M, int N, int K) {
    extern __shared__ uint32_t sm[];
    uint32_t* stA[2] = { sm,              sm + STAGE_F };
    uint32_t* stB[2] = { sm + A_STAGE_F,  sm + STAGE_F + A_STAGE_F };

    int tid = threadIdx.x;
    int lane = tid & 31, wid = tid >> 5;
    int warpM = wid & 1, warpN = wid >> 1;
    int row0 = blockIdx.y * 128, col0 = blockIdx.x * 128;

    float c[4][4][4];
    #pragma unroll
    for (int mf = 0; mf < 4; mf++)
        #pragma unroll
        for (int nf = 0; nf < 4; nf++)
            #pragma unroll
            for (int q = 0; q < 4; q++) c[mf][nf][q] = 0.0f;

    int nk = K / 32;
    {
        float4 av[4], bv[4];
        gload(A, BT, K, row0, col0, 0, tid, av, bv);
        stage_store(stA[0], stB[0], av, bv, tid);
    }
    __syncthreads();

    for (int kt = 0; kt < nk; kt++) {
        int s = kt & 1;
        float4 av[4], bv[4];
        if (kt + 1 < nk)
            gload(A, BT, K, row0, col0, (kt + 1) * 32, tid, av, bv);

        uint32_t* sA = stA[s];
        uint32_t* sB = stB[s];
        #pragma unroll
        for (int ss = 0; ss < 4; ss++) {
            uint32_t a[4][4], b[4][2];
            #pragma unroll
            for (int mf = 0; mf < 4; mf++) {
                int fa = (warpM * 4 + mf) * 4 + ss;
                uint4 v = *(uint4*)&sA[fa * AST + lane * 4];
                a[mf][0] = v.x; a[mf][1] = v.y; a[mf][2] = v.z; a[mf][3] = v.w;
            }
            #pragma unroll
            for (int nf = 0; nf < 4; nf++) {
                int fb = (warpN * 4 + nf) * 4 + ss;
                uint2 v = *(uint2*)&sB[fb * BST + lane * 2];
                b[nf][0] = v.x; b[nf][1] = v.y;
            }
            #pragma unroll
            for (int mf = 0; mf < 4; mf++)
                #pragma unroll
                for (int nf = 0; nf < 4; nf++)
                    mma_tf32(c[mf][nf], a[mf], b[nf]);
        }

        if (kt + 1 < nk) {
            stage_store(stA[s ^ 1], stB[s ^ 1], av, bv, tid);
            __syncthreads();
        }
    }

    int gid = lane >> 2, tig = lane & 3;
    #pragma unroll
    for (int mf = 0; mf < 4; mf++) {
        #pragma unroll
        for (int nf = 0; nf < 4; nf++) {
            int col = col0 + warpN * 32 + nf * 8 + tig * 2;
            float b0 = bias[col], b1 = bias[col + 1];
            #pragma unroll
            for (int h = 0; h < 2; h++) {
                int row = row0 + warpM * 64 + mf * 16 + gid + h * 8;
                float v0 = c[mf][nf][h * 2 + 0] + b0;
                float v1 = c[mf][nf][h * 2 + 1] + b1;
                if (EPI == 1) {
                    v0 = 0.5f * v0 * (1.0f + erff(v0 * 0.70710678118654752f));
                    v1 = 0.5f * v1 * (1.0f + erff(v1 * 0.70710678118654752f));
                } else if (EPI == 2) {
                    float2 rr = *(const float2*)&res[(size_t)row * N + col];
                    v0 += rr.x; v1 += rr.y;
                }
                float2 o; o.x = v0; o.y = v1;
                *(float2*)&C[(size_t)row * N + col] = o;
            }
        }
    }
}

// ======================= mma.sync tf32 flash attention =======================
// CTA: 128 q-rows x 1 head; 8 warps x 16 rows; key tile 64; Dh=64.
// K and V^T staged in fragment-order SMEM blocks (stride 66 floats).
// Fused epilogue: x1 = x + attn (raw-reshape flat add).

#define ATT_BST 66
#define ATT_OP_F (64 * ATT_BST)          // 4224 floats per operand per stage
#define ATT_STAGE_F (2 * ATT_OP_F)
#define ATT_SMEM_BYTES (2 * ATT_STAGE_F * 4)   // 67584 B

__device__ __forceinline__ void att_gload(const float* __restrict__ kb,
                                          const float* __restrict__ vb,
                                          int kt0, int tid, float4* kv, float4* vv) {
    #pragma unroll
    for (int l = 0; l < 4; l++) {
        int f = tid + l * 256;
        int r = f >> 4;                  // key row 0..63
        int i = f & 15;                  // float4 over dh
        kv[l] = *(const float4*)&kb[(size_t)(kt0 + r) * D3 + i * 4];
        vv[l] = *(const float4*)&vb[(size_t)(kt0 + r) * D3 + i * 4];
    }
}

__device__ __forceinline__ void att_stage(uint32_t* sK, uint32_t* sV,
                                          const float4* kv, const float4* vv,
                                          int tid) {
    #pragma unroll
    for (int l = 0; l < 4; l++) {
        int f = tid + l * 256;
        int r = f >> 4;
        int i = f & 15;
        // K as B operand: n=key=r, k=dh=i*4+q. block=(r>>3)*8 + (i>>1)
        {
            uint32_t* base = sK + ((r >> 3) * 8 + (i >> 1)) * ATT_BST + (i & 1);
            int ln0 = (r & 7) * 4;
            base[(ln0 + 0) * 2] = f2tf32(kv[l].x);
            base[(ln0 + 1) * 2] = f2tf32(kv[l].y);
            base[(ln0 + 2) * 2] = f2tf32(kv[l].z);
            base[(ln0 + 3) * 2] = f2tf32(kv[l].w);
        }
        // V^T as B operand: n=dh=i*4+q, k=key=r. block=(i>>1)*8 + (r>>3)
        {
            int regid = (r >> 2) & 1;
            uint32_t* base = sV + ((i >> 1) * 8 + (r >> 3)) * ATT_BST + regid;
            int lq = (((i & 1) * 4) * 4 + (r & 3)) * 2;   // word offset for q=0
            base[lq + 0]  = f2tf32(vv[l].x);
            base[lq + 8]  = f2tf32(vv[l].y);
            base[lq + 16] = f2tf32(vv[l].z);
            base[lq + 24] = f2tf32(vv[l].w);
        }
    }
}

__global__ __launch_bounds__(256) void attn_mma(const float* __restrict__ qkv,
                                                const float* __restrict__ x,
                                                float* __restrict__ x1) {
    extern __shared__ uint32_t smA[];
    uint32_t* stK[2] = { smA,              smA + ATT_STAGE_F };
    uint32_t* stV[2] = { smA + ATT_OP_F,   smA + ATT_STAGE_F + ATT_OP_F };

    int tid = threadIdx.x, lane = tid & 31, w = tid >> 5;
    int gid = lane >> 2, tig = lane & 3;
    int bh = blockIdx.y;
    int b = bh >> 4, h = bh & 15;
    int q0 = blockIdx.x * 128;

    const float* qbase = qkv + (size_t)b * NN * D3 + h * DHH;
    const float* kbase = qbase + DD;
    const float* vbase = qbase + 2 * DD;

    // Q fragments (held for whole KV loop)
    uint32_t qa[8][4];
    {
        const float* Q0 = qbase + (size_t)(q0 + w * 16 + gid) * D3;
        const float* Q1 = Q0 + 8 * D3;
        #pragma unroll
        for (int ks = 0; ks < 8; ks++) {
            qa[ks][0] = f2tf32(Q0[ks * 8 + tig]);
            qa[ks][1] = f2tf32(Q1[ks * 8 + tig]);
            qa[ks][2] = f2tf32(Q0[ks * 8 + tig + 4]);
            qa[ks][3] = f2tf32(Q1[ks * 8 + tig + 4]);
        }
    }

    float o[8][4];
    #pragma unroll
    for (int nd = 0; nd < 8; nd++)
        #pragma unroll
        for (int q = 0; q < 4; q++) o[nd][q] = 0.0f;
    float m0 = -1e30f, m1 = -1e30f, l0 = 0.0f, l1 = 0.0f;

    float4 kv[4], vv[4];
    att_gload(kbase, vbase, 0, tid, kv, vv);
    att_stage(stK[0], stV[0], kv, vv, tid);
    __syncthreads();

    for (int kt = 0; kt < NN / 64; kt++) {
        int s = kt & 1;
        if (kt + 1 < NN / 64)
            att_gload(kbase, vbase, (kt + 1) * 64, tid, kv, vv);

        // ---- S = Q @ K^T (16 x 64 per warp) ----
        float c[8][4];
        #pragma unroll
        for (int nf = 0; nf < 8; nf++)
            #pragma unroll
            for (int q = 0; q < 4; q++) c[nf][q] = 0.0f;
        #pragma unroll
        for (int ks = 0; ks < 8; ks++) {
            #pragma unroll
            for (int nf = 0; nf < 8; nf++) {
                uint2 bb = *(uint2*)&stK[s][(nf * 8 + ks) * ATT_BST + lane * 2];
                uint32_t br[2] = { bb.x, bb.y };
                mma_tf32(c[nf], qa[ks], br);
            }
        }

        // ---- online softmax ----
        float mx0 = -1e30f, mx1 = -1e30f;
        #pragma unroll
        for (int nf = 0; nf < 8; nf++) {
            mx0 = fmaxf(mx0, fmaxf(c[nf][0], c[nf][1]));
            mx1 = fmaxf(mx1, fmaxf(c[nf][2], c[nf][3]));
        }
        mx0 = fmaxf(mx0, __shfl_xor_sync(0xffffffffu, mx0, 1));
        mx0 = fmaxf(mx0, __shfl_xor_sync(0xffffffffu, mx0, 2));
        mx1 = fmaxf(mx1, __shfl_xor_sync(0xffffffffu, mx1, 1));
        mx1 = fmaxf(mx1, __shfl_xor_sync(0xffffffffu, mx1, 2));
        float m0n = fmaxf(m0, mx0), m1n = fmaxf(m1, mx1);
        float sc0 = __expf(m0 - m0n), sc1 = __expf(m1 - m1n);
        m0 = m0n; m1 = m1n;

        float rs0 = 0.0f, rs1 = 0.0f;
        #pragma unroll
        for (int nf = 0; nf < 8; nf++) {
            c[nf][0] = __expf(c[nf][0] - m0n);
            c[nf][1] = __expf(c[nf][1] - m0n);
            c[nf][2] = __expf(c[nf][2] - m1n);
            c[nf][3] = __expf(c[nf][3] - m1n);
            rs0 += c[nf][0] + c[nf][1];
            rs1 += c[nf][2] + c[nf][3];
        }
        rs0 += __shfl_xor_sync(0xffffffffu, rs0, 1);
        rs0 += __shfl_xor_sync(0xffffffffu, rs0, 2);
        rs1 += __shfl_xor_sync(0xffffffffu, rs1, 1);
        rs1 += __shfl_xor_sync(0xffffffffu, rs1, 2);
        l0 = l0 * sc0 + rs0;
        l1 = l1 * sc1 + rs1;
        #pragma unroll
        for (int nd = 0; nd < 8; nd++) {
            o[nd][0] *= sc0; o[nd][1] *= sc0;
            o[nd][2] *= sc1; o[nd][3] *= sc1;
        }

        // ---- O += P @ V ----
        int s0l = (lane & ~3) | (tig >> 1);
        int s1l = s0l + 2;
        bool odd = (tig & 1) != 0;
        #pragma unroll
        for (int ks = 0; ks < 8; ks++) {
            float v00 = __shfl_sync(0xffffffffu, c[ks][0], s0l);
            float v01 = __shfl_sync(0xffffffffu, c[ks][1], s0l);
            float v10 = __shfl_sync(0xffffffffu, c[ks][0], s1l);
            float v11 = __shfl_sync(0xffffffffu, c[ks][1], s1l);
            float w00 = __shfl_sync(0xffffffffu, c[ks][2], s0l);
            float w01 = __shfl_sync(0xffffffffu, c[ks][3], s0l);
            float w10 = __shfl_sync(0xffffffffu, c[ks][2], s1l);
            float w11 = __shfl_sync(0xffffffffu, c[ks][3], s1l);
            uint32_t pa[4];
            pa[0] = f2tf32(odd ? v01 : v00);
            pa[1] = f2tf32(odd ? w01 : w00);
            pa[2] = f2tf32(odd ? v11 : v10);
            pa[3] = f2tf32(odd ? w11 : w10);
            #pragma unroll
            for (int nd = 0; nd < 8; nd++) {
                uint2 bb = *(uint2*)&stV[s][(nd * 8 + ks) * ATT_BST + lane * 2];
                uint32_t br[2] = { bb.x, bb.y };
                mma_tf32(o[nd], pa, br);
            }
        }

        if (kt + 1 < NN / 64) {
            att_stage(stK[s ^ 1], stV[s ^ 1], kv, vv, tid);
            __syncthreads();
        }
    }

    // ---- epilogue: x1 = x + attn ([B,H,N,Dh] flat == [B,N,D] flat) ----
    float i0 = 1.0f / l0, i1 = 1.0f / l1;
    size_t ob = ((size_t)bh * NN + q0 + w * 16) * DHH;
    #pragma unroll
    for (int nd = 0; nd < 8; nd++) {
        int col = nd * 8 + tig * 2;
        size_t f0 = ob + (size_t)gid * DHH + col;
        size_t f1 = f0 + 8 * DHH;
        float2 x0 = *(const float2*)&x[f0];
        float2 xx1 = *(const float2*)&x[f1];
        float2 o0, o1;
        o0.x = x0.x + o[nd][0] * i0;
        o0.y = x0.y + o[nd][1] * i0;
        o1.x = xx1.x + o[nd][2] * i1;
        o1.y = xx1.y + o[nd][3] * i1;
        *(float2*)&x1[f0] = o0;
        *(float2*)&x1[f1] = o1;
    }
}

// ---------------- weight transpose: out[C][R] = in[R][C] ---------------------
__global__ __launch_bounds__(256) void transpose_kernel(const float* __restrict__ in,
                                                        float* __restrict__ out,
                                                        int R, int C) {
    __shared__ float t[32][33];
    int c0 = blockIdx.x * 32, r0 = blockIdx.y * 32;
    int tx = threadIdx.x & 31, ty8 = threadIdx.x >> 5;
    #pragma unroll
    for (int l = 0; l < 4; l++) {
        int r = ty8 + l * 8;
        t[r][tx] = in[(size_t)(r0 + r) * C + c0 + tx];
    }
    __syncthreads();
    #pragma unroll
    for (int l = 0; l < 4; l++) {
        int r = ty8 + l * 8;
        out[(size_t)(c0 + r) * R + r0 + tx] = t[tx][r];
    }
}

// ---------------- block reduce helper ---------------------------------------
__device__ __forceinline__ float block_sum_256(float v) {
    __shared__ float red[8];
    #pragma unroll
    for (int o = 16; o; o >>= 1) v += __shfl_xor_sync(0xffffffffu, v, o);
    int w = threadIdx.x >> 5;
    if ((threadIdx.x & 31) == 0) red[w] = v;
    __syncthreads();
    v = red[threadIdx.x & 7];
    #pragma unroll
    for (int o = 4; o; o >>= 1) v += __shfl_xor_sync(0xffffffffu, v, o);
    __syncthreads();
    return v;
}

// ---------------- LayerNorm ---------------------------------------------------
__global__ __launch_bounds__(256) void ln_kernel(const float* __restrict__ x,
                                                 const float* __restrict__ g,
                                                 const float* __restrict__ b,
                                                 float* __restrict__ out) {
    int row = blockIdx.x;
    const float4* xr = (const float4*)(x + (size_t)row * DD);
    float4 v = xr[threadIdx.x];
    float s = v.x + v.y + v.z + v.w;
    s = block_sum_256(s);
    float mu = s * (1.0f / DD);
    float dx = v.x - mu, dy = v.y - mu, dz = v.z - mu, dw = v.w - mu;
    float vs = dx*dx + dy*dy + dz*dz + dw*dw;
    vs = block_sum_256(vs);
    float rstd = rsqrtf(vs * (1.0f / DD) + 1e-5f);
    float4 gg = ((const float4*)g)[threadIdx.x];
    float4 bb = ((const float4*)b)[threadIdx.x];
    float4 o;
    o.x = dx * rstd * gg.x + bb.x;
    o.y = dy * rstd * gg.y + bb.y;
    o.z = dz * rstd * gg.z + bb.z;
    o.w = dw * rstd * gg.w + bb.w;
    ((float4*)(out + (size_t)row * DD))[threadIdx.x] = o;
}

// ---------------- launch ------------------------------------------------------
extern "C" void kernel_launch(void* const* d_in, const int* in_sizes, int n_in,
                              void* d_out, int out_size) {
    const float* x     = (const float*)d_in[0];
    const float* w_qkv = (const float*)d_in[1];
    const float* b_qkv = (const float*)d_in[2];
    const float* ln_g  = (const float*)d_in[3];
    const float* ln_b  = (const float*)d_in[4];
    const float* w1    = (const float*)d_in[5];
    const float* b1    = (const float*)d_in[6];
    const float* w2    = (const float*)d_in[7];
    const float* b2    = (const float*)d_in[8];
    float* out = (float*)d_out;

    float *xn, *qkv, *x1, *hbuf, *wqkvT, *w1T, *w2T;
    cudaGetSymbolAddress((void**)&xn,    g_xn);
    cudaGetSymbolAddress((void**)&qkv,   g_qkv);
    cudaGetSymbolAddress((void**)&x1,    g_x1);
    cudaGetSymbolAddress((void**)&hbuf,  g_h);
    cudaGetSymbolAddress((void**)&wqkvT, g_wqkvT);
    cudaGetSymbolAddress((void**)&w1T,   g_w1T);
    cudaGetSymbolAddress((void**)&w2T,   g_w2T);

    cudaFuncSetAttribute(gemm_mma<0>, cudaFuncAttributeMaxDynamicSharedMemorySize, GEMM_SMEM_BYTES);
    cudaFuncSetAttribute(gemm_mma<1>, cudaFuncAttributeMaxDynamicSharedMemorySize, GEMM_SMEM_BYTES);
    cudaFuncSetAttribute(gemm_mma<2>, cudaFuncAttributeMaxDynamicSharedMemorySize, GEMM_SMEM_BYTES);
    cudaFuncSetAttribute(attn_mma,    cudaFuncAttributeMaxDynamicSharedMemorySize, ATT_SMEM_BYTES);

    // 0. transpose weights (K-major B operands)
    transpose_kernel<<<dim3(D3 / 32, DD / 32), 256>>>(w_qkv, wqkvT, DD, D3);
    transpose_kernel<<<dim3(HID / 32, DD / 32), 256>>>(w1, w1T, DD, HID);
    transpose_kernel<<<dim3(DD / 32, HID / 32), 256>>>(w2, w2T, HID, DD);

    // 1. xn = LN(x)
    ln_kernel<<<ROWS, 256>>>(x, ln_g, ln_b, xn);
    // 2. qkv = xn @ w_qkv + b_qkv
    gemm_mma<0><<<dim3(D3 / 128, ROWS / 128), 256, GEMM_SMEM_BYTES>>>(
        xn, wqkvT, b_qkv, nullptr, qkv, ROWS, D3, DD);
    // 3+4. attention fused with residual: x1 = x + attn
    attn_mma<<<dim3(NN / 128, BB * HH), 256, ATT_SMEM_BYTES>>>(qkv, x, x1);
    // 5. xn = LN(x1)
    ln_kernel<<<ROWS, 256>>>(x1, ln_g, ln_b, xn);
    // 6. h = gelu(xn @ w1 + b1)
    gemm_mma<1><<<dim3(HID / 128, ROWS / 128), 256, GEMM_SMEM_BYTES>>>(
        xn, w1T, b1, nullptr, hbuf, ROWS, HID, DD);
    // 7. out = x1 + h @ w2 + b2
    gemm_mma<2><<<dim3(DD / 128, ROWS / 128), 256, GEMM_SMEM_BYTES>>>(
        hbuf, w2T, b2, x1, out, ROWS, DD, HID);
}

// round 7
// speedup vs baseline: 2.5652x; 1.1798x over previous
#include <cuda_runtime.h>
#include <cuda_bf16.h>
#include <math.h>
#include <stdint.h>

// Problem dims (fixed by reference)
#define BB 2
#define NN 2048
#define DD 1024
#define HH 16
#define DHH 64
#define HID 4096
#define D3 3072
#define ROWS (BB*NN)          // 4096

// ---------------- scratch (static device arrays; no allocation) -------------
__device__ float g_xn[ROWS * DD];
__device__ float g_qkv[ROWS * D3];
__device__ float g_x1[ROWS * DD];
__device__ float g_h[ROWS * HID];
__device__ float g_wqkvT[D3 * DD];
__device__ float g_w1T[HID * DD];
__device__ float g_w2T[DD * HID];

// ======================= common helpers ======================================
__device__ __forceinline__ uint32_t smem_u32(const void* p) {
    uint32_t a;
    asm("{ .reg .u64 t; cvta.to.shared.u64 t, %1; cvt.u32.u64 %0, t; }"
        : "=r"(a) : "l"(p));
    return a;
}

__device__ __forceinline__ uint32_t f2tf32(float x) {
    uint32_t u;
    asm("cvt.rna.tf32.f32 %0, %1;" : "=r"(u) : "f"(x));
    return u;
}

// rna-equivalent rounding for HMMA-tf32 consumers: HMMA ignores the low 13
// mantissa bits, so bits+0x1000 (round half away) == cvt.rna.tf32.
#define RNA(u) ((u) + 0x1000u)

__device__ __forceinline__ void mma_tf32(float* c, const uint32_t* a, const uint32_t* b) {
    asm volatile(
        "mma.sync.aligned.m16n8k8.row.col.f32.tf32.tf32.f32 "
        "{%0,%1,%2,%3}, {%4,%5,%6,%7}, {%8,%9}, {%0,%1,%2,%3};"
        : "+f"(c[0]), "+f"(c[1]), "+f"(c[2]), "+f"(c[3])
        : "r"(a[0]), "r"(a[1]), "r"(a[2]), "r"(a[3]), "r"(b[0]), "r"(b[1]));
}

__device__ __forceinline__ void cpa4(uint32_t dst, const float* src) {
    asm volatile("cp.async.ca.shared.global [%0], [%1], 4;" :: "r"(dst), "l"(src));
}
#define CP_COMMIT() asm volatile("cp.async.commit_group;" ::: "memory")
#define CP_WAIT2()  asm volatile("cp.async.wait_group 2;" ::: "memory")

// ======================= mma.sync tf32 GEMM ==================================
// C[M,N] = A[M,K] @ BT[N,K]^T + bias; EPI: 0 bias, 1 gelu, 2 +res
// CTA tile 128x128x32, 256 threads (8 warps, 2x4), warp tile 64x32.
// 3-stage cp.async pipeline; raw fp32 staged in fragment order; rna in consumer.

#define AST 132
#define BST 66
#define A_STAGE_F (32 * AST)           // 4224 floats
#define B_STAGE_F (64 * BST)           // 4224 floats
#define STAGE_F (A_STAGE_F + B_STAGE_F)
#define GEMM_SMEM_BYTES (3 * STAGE_F * 4)   // 101376 B

__device__ __forceinline__ void gemm_cp_stage(uint32_t sA, uint32_t sB,
                                              const float* __restrict__ A,
                                              const float* __restrict__ BT,
                                              int K, int row0, int col0, int k0,
                                              int tid) {
    #pragma unroll
    for (int l = 0; l < 16; l++) {
        int f = tid + l * 256;         // 0..4095
        int r = f >> 5;                // 0..127
        int k = f & 31;
        uint32_t wa = (uint32_t)(((r >> 4) * 4 + (k >> 3)) * AST
                      + ((r & 7) * 4 + (k & 3)) * 4
                      + ((k >> 2) & 1) * 2 + ((r & 15) >= 8 ? 1 : 0));
        cpa4(sA + wa * 4, &A[(size_t)(row0 + r) * K + k0 + k]);
        uint32_t wb = (uint32_t)(((r >> 3) * 4 + (k >> 3)) * BST
                      + ((r & 7) * 4 + (k & 3)) * 2 + ((k >> 2) & 1));
        cpa4(sB + wb * 4, &BT[(size_t)(col0 + r) * K + k0 + k]);
    }
}

template<int EPI>
__global__ __launch_bounds__(256) void gemm_mma(const float* __restrict__ A,
                                                const float* __restrict__ BT,
                                                const float* __restrict__ bias,
                                                const float* __restrict__ res,
                                                float* __restrict__ C,
                                                int M, int N, int K) {
    extern __shared__ uint32_t sm[];
    uint32_t smb = smem_u32(sm);

    int tid = threadIdx.x;
    int lane = tid & 31, wid = tid >> 5;
    int warpM = wid & 1, warpN = wid >> 1;
    int row0 = blockIdx.y * 128, col0 = blockIdx.x * 128;

    float c[4][4][4];
    #pragma unroll
    for (int mf = 0; mf < 4; mf++)
        #pragma unroll
        for (int nf = 0; nf < 4; nf++)
            #pragma unroll
            for (int q = 0; q < 4; q++) c[mf][nf][q] = 0.0f;

    int nk = K / 32;
    gemm_cp_stage(smb, smb + A_STAGE_F * 4, A, BT, K, row0, col0, 0, tid);
    CP_COMMIT();
    gemm_cp_stage(smb + STAGE_F * 4, smb + (STAGE_F + A_STAGE_F) * 4,
                  A, BT, K, row0, col0, 32, tid);
    CP_COMMIT();

    for (int kt = 0; kt < nk; kt++) {
        int s = kt % 3;
        int kn = kt + 2;
        if (kn < nk) {
            int sn = kn % 3;
            gemm_cp_stage(smb + sn * STAGE_F * 4,
                          smb + (sn * STAGE_F + A_STAGE_F) * 4,
                          A, BT, K, row0, col0, kn * 32, tid);
        }
        CP_COMMIT();
        CP_WAIT2();
        __syncthreads();

        uint32_t* sA = sm + s * STAGE_F;
        uint32_t* sB = sA + A_STAGE_F;
        #pragma unroll
        for (int ss = 0; ss < 4; ss++) {
            uint32_t a[4][4], b[4][2];
            #pragma unroll
            for (int mf = 0; mf < 4; mf++) {
                int fa = (warpM * 4 + mf) * 4 + ss;
                uint4 v = *(uint4*)&sA[fa * AST + lane * 4];
                a[mf][0] = RNA(v.x); a[mf][1] = RNA(v.y);
                a[mf][2] = RNA(v.z); a[mf][3] = RNA(v.w);
            }
            #pragma unroll
            for (int nf = 0; nf < 4; nf++) {
                int fb = (warpN * 4 + nf) * 4 + ss;
                uint2 v = *(uint2*)&sB[fb * BST + lane * 2];
                b[nf][0] = RNA(v.x); b[nf][1] = RNA(v.y);
            }
            #pragma unroll
            for (int mf = 0; mf < 4; mf++)
                #pragma unroll
                for (int nf = 0; nf < 4; nf++)
                    mma_tf32(c[mf][nf], a[mf], b[nf]);
        }
        __syncthreads();
    }

    int gid = lane >> 2, tig = lane & 3;
    #pragma unroll
    for (int mf = 0; mf < 4; mf++) {
        #pragma unroll
        for (int nf = 0; nf < 4; nf++) {
            int col = col0 + warpN * 32 + nf * 8 + tig * 2;
            float b0 = bias[col], b1 = bias[col + 1];
            #pragma unroll
            for (int h = 0; h < 2; h++) {
                int row = row0 + warpM * 64 + mf * 16 + gid + h * 8;
                float v0 = c[mf][nf][h * 2 + 0] + b0;
                float v1 = c[mf][nf][h * 2 + 1] + b1;
                if (EPI == 1) {
                    v0 = 0.5f * v0 * (1.0f + erff(v0 * 0.70710678118654752f));
                    v1 = 0.5f * v1 * (1.0f + erff(v1 * 0.70710678118654752f));
                } else if (EPI == 2) {
                    float2 rr = *(const float2*)&res[(size_t)row * N + col];
                    v0 += rr.x; v1 += rr.y;
                }
                float2 o; o.x = v0; o.y = v1;
                *(float2*)&C[(size_t)row * N + col] = o;
            }
        }
    }
}

// ======================= mma.sync tf32 flash attention =======================
// CTA: 128 q-rows x 1 head; 8 warps x 16 rows; key tile 64; Dh=64.
// K and V^T raw fp32 in fragment-order SMEM, 3-stage cp.async pipeline;
// rna rounding applied in consumer fragment registers.
// Fused epilogue: x1 = x + attn (raw-reshape flat add).

#define ATT_BST 66
#define ATT_OP_F (64 * ATT_BST)          // 4224 floats per operand
#define ATT_STAGE_F (2 * ATT_OP_F)
#define ATT_SMEM_BYTES (3 * ATT_STAGE_F * 4)   // 101376 B

__device__ __forceinline__ void att_cp_stage(uint32_t sK, uint32_t sV,
                                             const float* __restrict__ kb,
                                             const float* __restrict__ vb,
                                             int kt0, int tid) {
    #pragma unroll
    for (int l = 0; l < 16; l++) {
        int f = tid + l * 256;           // 0..4095
        int r = f >> 6;                  // key row 0..63
        int d = f & 63;                  // dh
        uint32_t wk = (uint32_t)(((r >> 3) * 8 + (d >> 3)) * ATT_BST
                      + ((r & 7) * 4 + (d & 3)) * 2 + ((d >> 2) & 1));
        cpa4(sK + wk * 4, &kb[(size_t)(kt0 + r) * D3 + d]);
        uint32_t wv = (uint32_t)(((d >> 3) * 8 + (r >> 3)) * ATT_BST
                      + ((d & 7) * 4 + (r & 3)) * 2 + ((r >> 2) & 1));
        cpa4(sV + wv * 4, &vb[(size_t)(kt0 + r) * D3 + d]);
    }
}

__global__ __launch_bounds__(256) void attn_mma(const float* __restrict__ qkv,
                                                const float* __restrict__ x,
                                                float* __restrict__ x1) {
    extern __shared__ uint32_t smA[];
    uint32_t smb = smem_u32(smA);

    int tid = threadIdx.x, lane = tid & 31, w = tid >> 5;
    int gid = lane >> 2, tig = lane & 3;
    int bh = blockIdx.y;
    int b = bh >> 4, h = bh & 15;
    int q0 = blockIdx.x * 128;

    const float* qbase = qkv + (size_t)b * NN * D3 + h * DHH;
    const float* kbase = qbase + DD;
    const float* vbase = qbase + 2 * DD;

    att_cp_stage(smb, smb + ATT_OP_F * 4, kbase, vbase, 0, tid);
    CP_COMMIT();
    att_cp_stage(smb + ATT_STAGE_F * 4, smb + (ATT_STAGE_F + ATT_OP_F) * 4,
                 kbase, vbase, 64, tid);
    CP_COMMIT();

    // Q fragments (rna tf32, held for whole KV loop)
    uint32_t qa[8][4];
    {
        const float* Q0 = qbase + (size_t)(q0 + w * 16 + gid) * D3;
        const float* Q1 = Q0 + 8 * D3;
        #pragma unroll
        for (int ks = 0; ks < 8; ks++) {
            qa[ks][0] = f2tf32(Q0[ks * 8 + tig]);
            qa[ks][1] = f2tf32(Q1[ks * 8 + tig]);
            qa[ks][2] = f2tf32(Q0[ks * 8 + tig + 4]);
            qa[ks][3] = f2tf32(Q1[ks * 8 + tig + 4]);
        }
    }

    float o[8][4];
    #pragma unroll
    for (int nd = 0; nd < 8; nd++)
        #pragma unroll
        for (int q = 0; q < 4; q++) o[nd][q] = 0.0f;
    float m0 = -1e30f, m1 = -1e30f, l0 = 0.0f, l1 = 0.0f;

    const int nt = NN / 64;
    for (int kt = 0; kt < nt; kt++) {
        int s = kt % 3;
        int kn = kt + 2;
        if (kn < nt) {
            int sn = kn % 3;
            att_cp_stage(smb + sn * ATT_STAGE_F * 4,
                         smb + (sn * ATT_STAGE_F + ATT_OP_F) * 4,
                         kbase, vbase, kn * 64, tid);
        }
        CP_COMMIT();
        CP_WAIT2();
        __syncthreads();

        uint32_t* sK = smA + s * ATT_STAGE_F;
        uint32_t* sV = sK + ATT_OP_F;

        // ---- S = Q @ K^T ----
        float c[8][4];
        #pragma unroll
        for (int nf = 0; nf < 8; nf++)
            #pragma unroll
            for (int q = 0; q < 4; q++) c[nf][q] = 0.0f;
        #pragma unroll
        for (int ks = 0; ks < 8; ks++) {
            #pragma unroll
            for (int nf = 0; nf < 8; nf++) {
                uint2 bb = *(uint2*)&sK[(nf * 8 + ks) * ATT_BST + lane * 2];
                uint32_t br[2] = { RNA(bb.x), RNA(bb.y) };
                mma_tf32(c[nf], qa[ks], br);
            }
        }

        // ---- online softmax ----
        float mx0 = -1e30f, mx1 = -1e30f;
        #pragma unroll
        for (int nf = 0; nf < 8; nf++) {
            mx0 = fmaxf(mx0, fmaxf(c[nf][0], c[nf][1]));
            mx1 = fmaxf(mx1, fmaxf(c[nf][2], c[nf][3]));
        }
        mx0 = fmaxf(mx0, __shfl_xor_sync(0xffffffffu, mx0, 1));
        mx0 = fmaxf(mx0, __shfl_xor_sync(0xffffffffu, mx0, 2));
        mx1 = fmaxf(mx1, __shfl_xor_sync(0xffffffffu, mx1, 1));
        mx1 = fmaxf(mx1, __shfl_xor_sync(0xffffffffu, mx1, 2));
        float m0n = fmaxf(m0, mx0), m1n = fmaxf(m1, mx1);
        float sc0 = __expf(m0 - m0n), sc1 = __expf(m1 - m1n);
        m0 = m0n; m1 = m1n;

        float rs0 = 0.0f, rs1 = 0.0f;
        #pragma unroll
        for (int nf = 0; nf < 8; nf++) {
            c[nf][0] = __expf(c[nf][0] - m0n);
            c[nf][1] = __expf(c[nf][1] - m0n);
            c[nf][2] = __expf(c[nf][2] - m1n);
            c[nf][3] = __expf(c[nf][3] - m1n);
            rs0 += c[nf][0] + c[nf][1];
            rs1 += c[nf][2] + c[nf][3];
        }
        rs0 += __shfl_xor_sync(0xffffffffu, rs0, 1);
        rs0 += __shfl_xor_sync(0xffffffffu, rs0, 2);
        rs1 += __shfl_xor_sync(0xffffffffu, rs1, 1);
        rs1 += __shfl_xor_sync(0xffffffffu, rs1, 2);
        l0 = l0 * sc0 + rs0;
        l1 = l1 * sc1 + rs1;
        #pragma unroll
        for (int nd = 0; nd < 8; nd++) {
            o[nd][0] *= sc0; o[nd][1] *= sc0;
            o[nd][2] *= sc1; o[nd][3] *= sc1;
        }

        // ---- O += P @ V ----
        int s0l = (lane & ~3) | (tig >> 1);
        int s1l = s0l + 2;
        bool odd = (tig & 1) != 0;
        #pragma unroll
        for (int ks = 0; ks < 8; ks++) {
            float v00 = __shfl_sync(0xffffffffu, c[ks][0], s0l);
            float v01 = __shfl_sync(0xffffffffu, c[ks][1], s0l);
            float v10 = __shfl_sync(0xffffffffu, c[ks][0], s1l);
            float v11 = __shfl_sync(0xffffffffu, c[ks][1], s1l);
            float w00 = __shfl_sync(0xffffffffu, c[ks][2], s0l);
            float w01 = __shfl_sync(0xffffffffu, c[ks][3], s0l);
            float w10 = __shfl_sync(0xffffffffu, c[ks][2], s1l);
            float w11 = __shfl_sync(0xffffffffu, c[ks][3], s1l);
            uint32_t pa[4];
            pa[0] = f2tf32(odd ? v01 : v00);
            pa[1] = f2tf32(odd ? w01 : w00);
            pa[2] = f2tf32(odd ? v11 : v10);
            pa[3] = f2tf32(odd ? w11 : w10);
            #pragma unroll
            for (int nd = 0; nd < 8; nd++) {
                uint2 bb = *(uint2*)&sV[(nd * 8 + ks) * ATT_BST + lane * 2];
                uint32_t br[2] = { RNA(bb.x), RNA(bb.y) };
                mma_tf32(o[nd], pa, br);
            }
        }
        __syncthreads();
    }

    // ---- epilogue: x1 = x + attn ([B,H,N,Dh] flat == [B,N,D] flat) ----
    float i0 = 1.0f / l0, i1 = 1.0f / l1;
    size_t ob = ((size_t)bh * NN + q0 + w * 16) * DHH;
    #pragma unroll
    for (int nd = 0; nd < 8; nd++) {
        int col = nd * 8 + tig * 2;
        size_t f0 = ob + (size_t)gid * DHH + col;
        size_t f1 = f0 + 8 * DHH;
        float2 x0 = *(const float2*)&x[f0];
        float2 xx1 = *(const float2*)&x[f1];
        float2 o0, o1;
        o0.x = x0.x + o[nd][0] * i0;
        o0.y = x0.y + o[nd][1] * i0;
        o1.x = xx1.x + o[nd][2] * i1;
        o1.y = xx1.y + o[nd][3] * i1;
        *(float2*)&x1[f0] = o0;
        *(float2*)&x1[f1] = o1;
    }
}

// ---------------- weight transpose: out[C][R] = in[R][C] ---------------------
__global__ __launch_bounds__(256) void transpose_kernel(const float* __restrict__ in,
                                                        float* __restrict__ out,
                                                        int R, int C) {
    __shared__ float t[32][33];
    int c0 = blockIdx.x * 32, r0 = blockIdx.y * 32;
    int tx = threadIdx.x & 31, ty8 = threadIdx.x >> 5;
    #pragma unroll
    for (int l = 0; l < 4; l++) {
        int r = ty8 + l * 8;
        t[r][tx] = in[(size_t)(r0 + r) * C + c0 + tx];
    }
    __syncthreads();
    #pragma unroll
    for (int l = 0; l < 4; l++) {
        int r = ty8 + l * 8;
        out[(size_t)(c0 + r) * R + r0 + tx] = t[tx][r];
    }
}

// ---------------- block reduce helper ---------------------------------------
__device__ __forceinline__ float block_sum_256(float v) {
    __shared__ float red[8];
    #pragma unroll
    for (int o = 16; o; o >>= 1) v += __shfl_xor_sync(0xffffffffu, v, o);
    int w = threadIdx.x >> 5;
    if ((threadIdx.x & 31) == 0) red[w] = v;
    __syncthreads();
    v = red[threadIdx.x & 7];
    #pragma unroll
    for (int o = 4; o; o >>= 1) v += __shfl_xor_sync(0xffffffffu, v, o);
    __syncthreads();
    return v;
}

// ---------------- LayerNorm ---------------------------------------------------
__global__ __launch_bounds__(256) void ln_kernel(const float* __restrict__ x,
                                                 const float* __restrict__ g,
                                                 const float* __restrict__ b,
                                                 float* __restrict__ out) {
    int row = blockIdx.x;
    const float4* xr = (const float4*)(x + (size_t)row * DD);
    float4 v = xr[threadIdx.x];
    float s = v.x + v.y + v.z + v.w;
    s = block_sum_256(s);
    float mu = s * (1.0f / DD);
    float dx = v.x - mu, dy = v.y - mu, dz = v.z - mu, dw = v.w - mu;
    float vs = dx*dx + dy*dy + dz*dz + dw*dw;
    vs = block_sum_256(vs);
    float rstd = rsqrtf(vs * (1.0f / DD) + 1e-5f);
    float4 gg = ((const float4*)g)[threadIdx.x];
    float4 bb = ((const float4*)b)[threadIdx.x];
    float4 o;
    o.x = dx * rstd * gg.x + bb.x;
    o.y = dy * rstd * gg.y + bb.y;
    o.z = dz * rstd * gg.z + bb.z;
    o.w = dw * rstd * gg.w + bb.w;
    ((float4*)(out + (size_t)row * DD))[threadIdx.x] = o;
}

// ---------------- launch ------------------------------------------------------
extern "C" void kernel_launch(void* const* d_in, const int* in_sizes, int n_in,
                              void* d_out, int out_size) {
    const float* x     = (const float*)d_in[0];
    const float* w_qkv = (const float*)d_in[1];
    const float* b_qkv = (const float*)d_in[2];
    const float* ln_g  = (const float*)d_in[3];
    const float* ln_b  = (const float*)d_in[4];
    const float* w1    = (const float*)d_in[5];
    const float* b1    = (const float*)d_in[6];
    const float* w2    = (const float*)d_in[7];
    const float* b2    = (const float*)d_in[8];
    float* out = (float*)d_out;

    float *xn, *qkv, *x1, *hbuf, *wqkvT, *w1T, *w2T;
    cudaGetSymbolAddress((void**)&xn,    g_xn);
    cudaGetSymbolAddress((void**)&qkv,   g_qkv);
    cudaGetSymbolAddress((void**)&x1,    g_x1);
    cudaGetSymbolAddress((void**)&hbuf,  g_h);
    cudaGetSymbolAddress((void**)&wqkvT, g_wqkvT);
    cudaGetSymbolAddress((void**)&w1T,   g_w1T);
    cudaGetSymbolAddress((void**)&w2T,   g_w2T);

    cudaFuncSetAttribute(gemm_mma<0>, cudaFuncAttributeMaxDynamicSharedMemorySize, GEMM_SMEM_BYTES);
    cudaFuncSetAttribute(gemm_mma<1>, cudaFuncAttributeMaxDynamicSharedMemorySize, GEMM_SMEM_BYTES);
    cudaFuncSetAttribute(gemm_mma<2>, cudaFuncAttributeMaxDynamicSharedMemorySize, GEMM_SMEM_BYTES);
    cudaFuncSetAttribute(attn_mma,    cudaFuncAttributeMaxDynamicSharedMemorySize, ATT_SMEM_BYTES);

    // 0. transpose weights (K-major B operands)
    transpose_kernel<<<dim3(D3 / 32, DD / 32), 256>>>(w_qkv, wqkvT, DD, D3);
    transpose_kernel<<<dim3(HID / 32, DD / 32), 256>>>(w1, w1T, DD, HID);
    transpose_kernel<<<dim3(DD / 32, HID / 32), 256>>>(w2, w2T, HID, DD);

    // 1. xn = LN(x)
    ln_kernel<<<ROWS, 256>>>(x, ln_g, ln_b, xn);
    // 2. qkv = xn @ w_qkv + b_qkv
    gemm_mma<0><<<dim3(D3 / 128, ROWS / 128), 256, GEMM_SMEM_BYTES>>>(
        xn, wqkvT, b_qkv, nullptr, qkv, ROWS, D3, DD);
    // 3+4. attention fused with residual: x1 = x + attn
    attn_mma<<<dim3(NN / 128, BB * HH), 256, ATT_SMEM_BYTES>>>(qkv, x, x1);
    // 5. xn = LN(x1)
    ln_kernel<<<ROWS, 256>>>(x1, ln_g, ln_b, xn);
    // 6. h = gelu(xn @ w1 + b1)
    gemm_mma<1><<<dim3(HID / 128, ROWS / 128), 256, GEMM_SMEM_BYTES>>>(
        xn, w1T, b1, nullptr, hbuf, ROWS, HID, DD);
    // 7. out = x1 + h @ w2 + b2
    gemm_mma<2><<<dim3(DD / 128, ROWS / 128), 256, GEMM_SMEM_BYTES>>>(
        hbuf, w2T, b2, x1, out, ROWS, DD, HID);
}

// round 10
// speedup vs baseline: 3.2851x; 1.2806x over previous
#include <cuda_runtime.h>
#include <cuda_bf16.h>
#include <math.h>
#include <stdint.h>

// Problem dims (fixed by reference)
#define BB 2
#define NN 2048
#define DD 1024
#define HH 16
#define DHH 64
#define HID 4096
#define D3 3072
#define ROWS (BB*NN)          // 4096

// ---------------- scratch (static device arrays; no allocation) -------------
__device__ float g_xn[ROWS * DD];
__device__ float g_qkv[ROWS * D3];
__device__ float g_x1[ROWS * DD];
__device__ float g_h[ROWS * HID];

// ======================= common helpers ======================================
__device__ __forceinline__ uint32_t smem_u32(const void* p) {
    uint32_t a;
    asm("{ .reg .u64 t; cvta.to.shared.u64 t, %1; cvt.u32.u64 %0, t; }"
        : "=r"(a) : "l"(p));
    return a;
}

__device__ __forceinline__ uint32_t f2tf32(float x) {
    uint32_t u;
    asm("cvt.rna.tf32.f32 %0, %1;" : "=r"(u) : "f"(x));
    return u;
}

// rna-equivalent rounding for HMMA-tf32 consumers: HMMA ignores the low 13
// mantissa bits, so bits+0x1000 (round half away) == cvt.rna.tf32.
#define RNA(u) ((u) + 0x1000u)

__device__ __forceinline__ void mma_tf32(float* c, const uint32_t* a, const uint32_t* b) {
    asm volatile(
        "mma.sync.aligned.m16n8k8.row.col.f32.tf32.tf32.f32 "
        "{%0,%1,%2,%3}, {%4,%5,%6,%7}, {%8,%9}, {%0,%1,%2,%3};"
        : "+f"(c[0]), "+f"(c[1]), "+f"(c[2]), "+f"(c[3])
        : "r"(a[0]), "r"(a[1]), "r"(a[2]), "r"(a[3]), "r"(b[0]), "r"(b[1]));
}

__device__ __forceinline__ void cpa4(uint32_t dst, const float* src) {
    asm volatile("cp.async.ca.shared.global [%0], [%1], 4;" :: "r"(dst), "l"(src));
}
__device__ __forceinline__ void cpa16(uint32_t dst, const float* src) {
    asm volatile("cp.async.cg.shared.global [%0], [%1], 16;" :: "r"(dst), "l"(src));
}
#define CP_COMMIT() asm volatile("cp.async.commit_group;" ::: "memory")
#define CP_WAIT2()  asm volatile("cp.async.wait_group 2;" ::: "memory")

// ======================= mma.sync tf32 GEMM ==================================
// C[M,N] = A[M,K] @ W[K,N] + bias; EPI: 0 bias, 1 gelu, 2 +res
// W consumed ROW-MAJOR directly (no pre-transpose).
// CTA tile 128x128x32, 256 threads (8 warps, 2x4), warp tile 64x32.
// 3-stage cp.async(16B) pipeline into padded row-major tiles:
//   A tile [128][KPAD=40], B tile [32][NPAD=136]; pad%32==8 makes all
//   scalar fragment LDS conflict-free. RNA rounding in consumer regs.

#define KPAD 40
#define NPAD 136
#define A_ST_F (128 * KPAD)            // 5120 floats
#define B_ST_F (32 * NPAD)             // 4352 floats
#define STAGE_F (A_ST_F + B_ST_F)      // 9472 floats
#define GEMM_SMEM_BYTES (3 * STAGE_F * 4)   // 113664 B

__device__ __forceinline__ void gemm_cp_stage(uint32_t sA, uint32_t sB,
                                              const float* __restrict__ A,
                                              const float* __restrict__ W,
                                              int K, int N, int row0, int col0,
                                              int k0, int tid) {
    #pragma unroll
    for (int l = 0; l < 4; l++) {
        int c = tid + l * 256;          // 0..1023
        int r = c >> 3;                 // A row 0..127
        int kc = c & 7;                 // 16B chunk in k
        cpa16(sA + (uint32_t)(r * KPAD + kc * 4) * 4,
              &A[(size_t)(row0 + r) * K + k0 + kc * 4]);
        int kr = c >> 5;                // B k-row 0..31
        int nc = c & 31;                // 16B chunk in n
        cpa16(sB + (uint32_t)(kr * NPAD + nc * 4) * 4,
              &W[(size_t)(k0 + kr) * N + col0 + nc * 4]);
    }
}

template<int EPI>
__global__ __launch_bounds__(256) void gemm_mma(const float* __restrict__ A,
                                                const float* __restrict__ W,
                                                const float* __restrict__ bias,
                                                const float* __restrict__ res,
                                                float* __restrict__ C,
                                                int M, int N, int K) {
    extern __shared__ uint32_t sm[];
    uint32_t smb = smem_u32(sm);

    int tid = threadIdx.x;
    int lane = tid & 31, wid = tid >> 5;
    int warpM = wid & 1, warpN = wid >> 1;
    int gid = lane >> 2, tig = lane & 3;
    int row0 = blockIdx.y * 128, col0 = blockIdx.x * 128;

    float c[4][4][4];
    #pragma unroll
    for (int mf = 0; mf < 4; mf++)
        #pragma unroll
        for (int nf = 0; nf < 4; nf++)
            #pragma unroll
            for (int q = 0; q < 4; q++) c[mf][nf][q] = 0.0f;

    int nk = K / 32;
    gemm_cp_stage(smb, smb + A_ST_F * 4, A, W, K, N, row0, col0, 0, tid);
    CP_COMMIT();
    gemm_cp_stage(smb + STAGE_F * 4, smb + (STAGE_F + A_ST_F) * 4,
                  A, W, K, N, row0, col0, 32, tid);
    CP_COMMIT();

    for (int kt = 0; kt < nk; kt++) {
        int s = kt % 3;
        int kn = kt + 2;
        if (kn < nk) {
            int sn = kn % 3;
            gemm_cp_stage(smb + sn * STAGE_F * 4,
                          smb + (sn * STAGE_F + A_ST_F) * 4,
                          A, W, K, N, row0, col0, kn * 32, tid);
        }
        CP_COMMIT();
        CP_WAIT2();
        __syncthreads();

        const uint32_t* sA = sm + s * STAGE_F;
        const uint32_t* sB = sA + A_ST_F;
        #pragma unroll
        for (int ss = 0; ss < 4; ss++) {
            uint32_t a[4][4], b[4][2];
            #pragma unroll
            for (int mf = 0; mf < 4; mf++) {
                int base = (warpM * 64 + mf * 16 + gid) * KPAD + ss * 8 + tig;
                a[mf][0] = RNA(sA[base]);
                a[mf][1] = RNA(sA[base + 8 * KPAD]);
                a[mf][2] = RNA(sA[base + 4]);
                a[mf][3] = RNA(sA[base + 8 * KPAD + 4]);
            }
            #pragma unroll
            for (int nf = 0; nf < 4; nf++) {
                int base = (ss * 8 + tig) * NPAD + warpN * 32 + nf * 8 + gid;
                b[nf][0] = RNA(sB[base]);
                b[nf][1] = RNA(sB[base + 4 * NPAD]);
            }
            #pragma unroll
            for (int mf = 0; mf < 4; mf++)
                #pragma unroll
                for (int nf = 0; nf < 4; nf++)
                    mma_tf32(c[mf][nf], a[mf], b[nf]);
        }
        __syncthreads();
    }

    #pragma unroll
    for (int mf = 0; mf < 4; mf++) {
        #pragma unroll
        for (int nf = 0; nf < 4; nf++) {
            int col = col0 + warpN * 32 + nf * 8 + tig * 2;
            float b0 = bias[col], b1 = bias[col + 1];
            #pragma unroll
            for (int h = 0; h < 2; h++) {
                int row = row0 + warpM * 64 + mf * 16 + gid + h * 8;
                float v0 = c[mf][nf][h * 2 + 0] + b0;
                float v1 = c[mf][nf][h * 2 + 1] + b1;
                if (EPI == 1) {
                    v0 = 0.5f * v0 * (1.0f + erff(v0 * 0.70710678118654752f));
                    v1 = 0.5f * v1 * (1.0f + erff(v1 * 0.70710678118654752f));
                } else if (EPI == 2) {
                    float2 rr = *(const float2*)&res[(size_t)row * N + col];
                    v0 += rr.x; v1 += rr.y;
                }
                float2 o; o.x = v0; o.y = v1;
                *(float2*)&C[(size_t)row * N + col] = o;
            }
        }
    }
}

// ======================= mma.sync tf32 flash attention =======================
// CTA: 128 q-rows x 1 head; 8 warps x 16 rows; key tile 64; Dh=64.
// K and V^T raw fp32 in fragment-order SMEM, 3-stage cp.async pipeline;
// rna rounding applied in consumer fragment registers.
// Fused epilogue: x1 = x + attn (raw-reshape flat add).

#define ATT_BST 66
#define ATT_OP_F (64 * ATT_BST)          // 4224 floats per operand
#define ATT_STAGE_F (2 * ATT_OP_F)
#define ATT_SMEM_BYTES (3 * ATT_STAGE_F * 4)   // 101376 B

__device__ __forceinline__ void att_cp_stage(uint32_t sK, uint32_t sV,
                                             const float* __restrict__ kb,
                                             const float* __restrict__ vb,
                                             int kt0, int tid) {
    #pragma unroll
    for (int l = 0; l < 16; l++) {
        int f = tid + l * 256;           // 0..4095
        int r = f >> 6;                  // key row 0..63
        int d = f & 63;                  // dh
        uint32_t wk = (uint32_t)(((r >> 3) * 8 + (d >> 3)) * ATT_BST
                      + ((r & 7) * 4 + (d & 3)) * 2 + ((d >> 2) & 1));
        cpa4(sK + wk * 4, &kb[(size_t)(kt0 + r) * D3 + d]);
        uint32_t wv = (uint32_t)(((d >> 3) * 8 + (r >> 3)) * ATT_BST
                      + ((d & 7) * 4 + (r & 3)) * 2 + ((r >> 2) & 1));
        cpa4(sV + wv * 4, &vb[(size_t)(kt0 + r) * D3 + d]);
    }
}

__global__ __launch_bounds__(256) void attn_mma(const float* __restrict__ qkv,
                                                const float* __restrict__ x,
                                                float* __restrict__ x1) {
    extern __shared__ uint32_t smA[];
    uint32_t smb = smem_u32(smA);

    int tid = threadIdx.x, lane = tid & 31, w = tid >> 5;
    int gid = lane >> 2, tig = lane & 3;
    int bh = blockIdx.y;
    int b = bh >> 4, h = bh & 15;
    int q0 = blockIdx.x * 128;

    const float* qbase = qkv + (size_t)b * NN * D3 + h * DHH;
    const float* kbase = qbase + DD;
    const float* vbase = qbase + 2 * DD;

    att_cp_stage(smb, smb + ATT_OP_F * 4, kbase, vbase, 0, tid);
    CP_COMMIT();
    att_cp_stage(smb + ATT_STAGE_F * 4, smb + (ATT_STAGE_F + ATT_OP_F) * 4,
                 kbase, vbase, 64, tid);
    CP_COMMIT();

    // Q fragments (rna tf32, held for whole KV loop)
    uint32_t qa[8][4];
    {
        const float* Q0 = qbase + (size_t)(q0 + w * 16 + gid) * D3;
        const float* Q1 = Q0 + 8 * D3;
        #pragma unroll
        for (int ks = 0; ks < 8; ks++) {
            qa[ks][0] = f2tf32(Q0[ks * 8 + tig]);
            qa[ks][1] = f2tf32(Q1[ks * 8 + tig]);
            qa[ks][2] = f2tf32(Q0[ks * 8 + tig + 4]);
            qa[ks][3] = f2tf32(Q1[ks * 8 + tig + 4]);
        }
    }

    float o[8][4];
    #pragma unroll
    for (int nd = 0; nd < 8; nd++)
        #pragma unroll
        for (int q = 0; q < 4; q++) o[nd][q] = 0.0f;
    float m0 = -1e30f, m1 = -1e30f, l0 = 0.0f, l1 = 0.0f;

    const int nt = NN / 64;
    for (int kt = 0; kt < nt; kt++) {
        int s = kt % 3;
        int kn = kt + 2;
        if (kn < nt) {
            int sn = kn % 3;
            att_cp_stage(smb + sn * ATT_STAGE_F * 4,
                         smb + (sn * ATT_STAGE_F + ATT_OP_F) * 4,
                         kbase, vbase, kn * 64, tid);
        }
        CP_COMMIT();
        CP_WAIT2();
        __syncthreads();

        uint32_t* sK = smA + s * ATT_STAGE_F;
        uint32_t* sV = sK + ATT_OP_F;

        // ---- S = Q @ K^T ----
        float c[8][4];
        #pragma unroll
        for (int nf = 0; nf < 8; nf++)
            #pragma unroll
            for (int q = 0; q < 4; q++) c[nf][q] = 0.0f;
        #pragma unroll
        for (int ks = 0; ks < 8; ks++) {
            #pragma unroll
            for (int nf = 0; nf < 8; nf++) {
                uint2 bb = *(uint2*)&sK[(nf * 8 + ks) * ATT_BST + lane * 2];
                uint32_t br[2] = { RNA(bb.x), RNA(bb.y) };
                mma_tf32(c[nf], qa[ks], br);
            }
        }

        // ---- online softmax ----
        float mx0 = -1e30f, mx1 = -1e30f;
        #pragma unroll
        for (int nf = 0; nf < 8; nf++) {
            mx0 = fmaxf(mx0, fmaxf(c[nf][0], c[nf][1]));
            mx1 = fmaxf(mx1, fmaxf(c[nf][2], c[nf][3]));
        }
        mx0 = fmaxf(mx0, __shfl_xor_sync(0xffffffffu, mx0, 1));
        mx0 = fmaxf(mx0, __shfl_xor_sync(0xffffffffu, mx0, 2));
        mx1 = fmaxf(mx1, __shfl_xor_sync(0xffffffffu, mx1, 1));
        mx1 = fmaxf(mx1, __shfl_xor_sync(0xffffffffu, mx1, 2));
        float m0n = fmaxf(m0, mx0), m1n = fmaxf(m1, mx1);
        float sc0 = __expf(m0 - m0n), sc1 = __expf(m1 - m1n);
        m0 = m0n; m1 = m1n;

        float rs0 = 0.0f, rs1 = 0.0f;
        #pragma unroll
        for (int nf = 0; nf < 8; nf++) {
            c[nf][0] = __expf(c[nf][0] - m0n);
            c[nf][1] = __expf(c[nf][1] - m0n);
            c[nf][2] = __expf(c[nf][2] - m1n);
            c[nf][3] = __expf(c[nf][3] - m1n);
            rs0 += c[nf][0] + c[nf][1];
            rs1 += c[nf][2] + c[nf][3];
        }
        rs0 += __shfl_xor_sync(0xffffffffu, rs0, 1);
        rs0 += __shfl_xor_sync(0xffffffffu, rs0, 2);
        rs1 += __shfl_xor_sync(0xffffffffu, rs1, 1);
        rs1 += __shfl_xor_sync(0xffffffffu, rs1, 2);
        l0 = l0 * sc0 + rs0;
        l1 = l1 * sc1 + rs1;
        #pragma unroll
        for (int nd = 0; nd < 8; nd++) {
            o[nd][0] *= sc0; o[nd][1] *= sc0;
            o[nd][2] *= sc1; o[nd][3] *= sc1;
        }

        // ---- O += P @ V ----
        int s0l = (lane & ~3) | (tig >> 1);
        int s1l = s0l + 2;
        bool odd = (tig & 1) != 0;
        #pragma unroll
        for (int ks = 0; ks < 8; ks++) {
            float v00 = __shfl_sync(0xffffffffu, c[ks][0], s0l);
            float v01 = __shfl_sync(0xffffffffu, c[ks][1], s0l);
            float v10 = __shfl_sync(0xffffffffu, c[ks][0], s1l);
            float v11 = __shfl_sync(0xffffffffu, c[ks][1], s1l);
            float w00 = __shfl_sync(0xffffffffu, c[ks][2], s0l);
            float w01 = __shfl_sync(0xffffffffu, c[ks][3], s0l);
            float w10 = __shfl_sync(0xffffffffu, c[ks][2], s1l);
            float w11 = __shfl_sync(0xffffffffu, c[ks][3], s1l);
            uint32_t pa[4];
            pa[0] = f2tf32(odd ? v01 : v00);
            pa[1] = f2tf32(odd ? w01 : w00);
            pa[2] = f2tf32(odd ? v11 : v10);
            pa[3] = f2tf32(odd ? w11 : w10);
            #pragma unroll
            for (int nd = 0; nd < 8; nd++) {
                uint2 bb = *(uint2*)&sV[(nd * 8 + ks) * ATT_BST + lane * 2];
                uint32_t br[2] = { RNA(bb.x), RNA(bb.y) };
                mma_tf32(o[nd], pa, br);
            }
        }
        __syncthreads();
    }

    // ---- epilogue: x1 = x + attn ([B,H,N,Dh] flat == [B,N,D] flat) ----
    float i0 = 1.0f / l0, i1 = 1.0f / l1;
    size_t ob = ((size_t)bh * NN + q0 + w * 16) * DHH;
    #pragma unroll
    for (int nd = 0; nd < 8; nd++) {
        int col = nd * 8 + tig * 2;
        size_t f0 = ob + (size_t)gid * DHH + col;
        size_t f1 = f0 + 8 * DHH;
        float2 x0 = *(const float2*)&x[f0];
        float2 xx1 = *(const float2*)&x[f1];
        float2 o0, o1;
        o0.x = x0.x + o[nd][0] * i0;
        o0.y = x0.y + o[nd][1] * i0;
        o1.x = xx1.x + o[nd][2] * i1;
        o1.y = xx1.y + o[nd][3] * i1;
        *(float2*)&x1[f0] = o0;
        *(float2*)&x1[f1] = o1;
    }
}

// ---------------- block reduce helper ---------------------------------------
__device__ __forceinline__ float block_sum_256(float v) {
    __shared__ float red[8];
    #pragma unroll
    for (int o = 16; o; o >>= 1) v += __shfl_xor_sync(0xffffffffu, v, o);
    int w = threadIdx.x >> 5;
    if ((threadIdx.x & 31) == 0) red[w] = v;
    __syncthreads();
    v = red[threadIdx.x & 7];
    #pragma unroll
    for (int o = 4; o; o >>= 1) v += __shfl_xor_sync(0xffffffffu, v, o);
    __syncthreads();
    return v;
}

// ---------------- LayerNorm ---------------------------------------------------
__global__ __launch_bounds__(256) void ln_kernel(const float* __restrict__ x,
                                                 const float* __restrict__ g,
                                                 const float* __restrict__ b,
                                                 float* __restrict__ out) {
    int row = blockIdx.x;
    const float4* xr = (const float4*)(x + (size_t)row * DD);
    float4 v = xr[threadIdx.x];
    float s = v.x + v.y + v.z + v.w;
    s = block_sum_256(s);
    float mu = s * (1.0f / DD);
    float dx = v.x - mu, dy = v.y - mu, dz = v.z - mu, dw = v.w - mu;
    float vs = dx*dx + dy*dy + dz*dz + dw*dw;
    vs = block_sum_256(vs);
    float rstd = rsqrtf(vs * (1.0f / DD) + 1e-5f);
    float4 gg = ((const float4*)g)[threadIdx.x];
    float4 bb = ((const float4*)b)[threadIdx.x];
    float4 o;
    o.x = dx * rstd * gg.x + bb.x;
    o.y = dy * rstd * gg.y + bb.y;
    o.z = dz * rstd * gg.z + bb.z;
    o.w = dw * rstd * gg.w + bb.w;
    ((float4*)(out + (size_t)row * DD))[threadIdx.x] = o;
}

// ---------------- launch ------------------------------------------------------
extern "C" void kernel_launch(void* const* d_in, const int* in_sizes, int n_in,
                              void* d_out, int out_size) {
    const float* x     = (const float*)d_in[0];
    const float* w_qkv = (const float*)d_in[1];
    const float* b_qkv = (const float*)d_in[2];
    const float* ln_g  = (const float*)d_in[3];
    const float* ln_b  = (const float*)d_in[4];
    const float* w1    = (const float*)d_in[5];
    const float* b1    = (const float*)d_in[6];
    const float* w2    = (const float*)d_in[7];
    const float* b2    = (const float*)d_in[8];
    float* out = (float*)d_out;

    float *xn, *qkv, *x1, *hbuf;
    cudaGetSymbolAddress((void**)&xn,   g_xn);
    cudaGetSymbolAddress((void**)&qkv,  g_qkv);
    cudaGetSymbolAddress((void**)&x1,   g_x1);
    cudaGetSymbolAddress((void**)&hbuf, g_h);

    cudaFuncSetAttribute(gemm_mma<0>, cudaFuncAttributeMaxDynamicSharedMemorySize, GEMM_SMEM_BYTES);
    cudaFuncSetAttribute(gemm_mma<1>, cudaFuncAttributeMaxDynamicSharedMemorySize, GEMM_SMEM_BYTES);
    cudaFuncSetAttribute(gemm_mma<2>, cudaFuncAttributeMaxDynamicSharedMemorySize, GEMM_SMEM_BYTES);
    cudaFuncSetAttribute(attn_mma,    cudaFuncAttributeMaxDynamicSharedMemorySize, ATT_SMEM_BYTES);

    // 1. xn = LN(x)
    ln_kernel<<<ROWS, 256>>>(x, ln_g, ln_b, xn);
    // 2. qkv = xn @ w_qkv + b_qkv   (w_qkv row-major, consumed directly)
    gemm_mma<0><<<dim3(D3 / 128, ROWS / 128), 256, GEMM_SMEM_BYTES>>>(
        xn, w_qkv, b_qkv, nullptr, qkv, ROWS, D3, DD);
    // 3+4. attention fused with residual: x1 = x + attn
    attn_mma<<<dim3(NN / 128, BB * HH), 256, ATT_SMEM_BYTES>>>(qkv, x, x1);
    // 5. xn = LN(x1)
    ln_kernel<<<ROWS, 256>>>(x1, ln_g, ln_b, xn);
    // 6. h = gelu(xn @ w1 + b1)
    gemm_mma<1><<<dim3(HID / 128, ROWS / 128), 256, GEMM_SMEM_BYTES>>>(
        xn, w1, b1, nullptr, hbuf, ROWS, HID, DD);
    // 7. out = x1 + h @ w2 + b2
    gemm_mma<2><<<dim3(DD / 128, ROWS / 128), 256, GEMM_SMEM_BYTES>>>(
        hbuf, w2, b2, x1, out, ROWS, DD, HID);
}